// round 1
// baseline (speedup 1.0000x reference)
#include <cuda_runtime.h>
#include <cuda_bf16.h>
#include <stdint.h>
#include <math.h>

#define CB 128
#define CS 128
#define CH 1024
#define CE 512
#define CV 32000

// ---------------- scratch (__device__ globals; no allocations allowed) -------
__device__ __align__(16) float g_hW[CB * CH];
__device__ __align__(16) float g_score[CB * CS];
__device__ __align__(16) float g_xin[CB * 2560];      // [emb(512)|context(1024)|h_last(1024)]
__device__ __align__(16) float g_gates[CB * 4096];
__device__ __align__(16) __nv_bfloat16 g_out2_hi[CB * 2048];  // [h_new | context]
__device__ __align__(16) __nv_bfloat16 g_out2_lo[CB * 2048];
__device__ __align__(16) __nv_bfloat16 g_enc_hi[CB * CS * CH];
__device__ __align__(16) __nv_bfloat16 g_enc_lo[CB * CS * CH];
__device__ __align__(16) __nv_bfloat16 g_w2_hi[CH * CH];      // attn_W[:, H:2H] as [n][k]
__device__ __align__(16) __nv_bfloat16 g_w2_lo[CH * CH];

// ---------------- helpers ----------------------------------------------------
__device__ __forceinline__ void splitf(float x, __nv_bfloat16 &hi, __nv_bfloat16 &lo) {
    hi = __float2bfloat16_rn(x);
    lo = __float2bfloat16_rn(x - __bfloat162float(hi));
}
__device__ __forceinline__ float sigf(float x) { return 1.0f / (1.0f + expf(-x)); }

#define MMA16816(d, a, b)                                                      \
    asm volatile(                                                              \
        "mma.sync.aligned.m16n8k16.row.col.f32.bf16.bf16.f32 "                 \
        "{%0,%1,%2,%3},{%4,%5,%6,%7},{%8,%9},{%0,%1,%2,%3};\n"                 \
        : "+f"(d[0]), "+f"(d[1]), "+f"(d[2]), "+f"(d[3])                       \
        : "r"(a[0]), "r"(a[1]), "r"(a[2]), "r"(a[3]), "r"(b[0]), "r"(b[1]))

// ---------------- precision split of encoder_outputs and attn_W[:,H:] --------
__global__ __launch_bounds__(256) void conv_enc_kernel(const float *__restrict__ enc) {
    size_t idx = (size_t)blockIdx.x * 256 + threadIdx.x;  // float4 index
    float4 v4 = ((const float4 *)enc)[idx];
    __nv_bfloat16 h0, h1, h2, h3, l0, l1, l2, l3;
    splitf(v4.x, h0, l0); splitf(v4.y, h1, l1);
    splitf(v4.z, h2, l2); splitf(v4.w, h3, l3);
    ((__nv_bfloat162 *)g_enc_hi)[idx * 2 + 0] = __halves2bfloat162(h0, h1);
    ((__nv_bfloat162 *)g_enc_hi)[idx * 2 + 1] = __halves2bfloat162(h2, h3);
    ((__nv_bfloat162 *)g_enc_lo)[idx * 2 + 0] = __halves2bfloat162(l0, l1);
    ((__nv_bfloat162 *)g_enc_lo)[idx * 2 + 1] = __halves2bfloat162(l2, l3);
}

__global__ __launch_bounds__(256) void conv_w2_kernel(const float *__restrict__ attn_W) {
    size_t idx = (size_t)blockIdx.x * 256 + threadIdx.x;  // float4 index, 262144 total
    int n = (int)(idx >> 8);
    int k = (int)(idx & 255) << 2;
    float4 v4 = *(const float4 *)(attn_W + (size_t)n * 2048 + 1024 + k);
    __nv_bfloat16 h0, h1, h2, h3, l0, l1, l2, l3;
    splitf(v4.x, h0, l0); splitf(v4.y, h1, l1);
    splitf(v4.z, h2, l2); splitf(v4.w, h3, l3);
    size_t o = ((size_t)n * CH + k) >> 1;
    ((__nv_bfloat162 *)g_w2_hi)[o + 0] = __halves2bfloat162(h0, h1);
    ((__nv_bfloat162 *)g_w2_hi)[o + 1] = __halves2bfloat162(h2, h3);
    ((__nv_bfloat162 *)g_w2_lo)[o + 0] = __halves2bfloat162(l0, l1);
    ((__nv_bfloat162 *)g_w2_lo)[o + 1] = __halves2bfloat162(l2, l3);
}

// ---------------- generic bf16-split x3 GEMM: C[M,N] = A@B^T (+bias) ---------
// A: fp32 [M,lda] (converted while staging) OR pre-split bf16 (Ahi/Alo != null).
// B rows n: k < ksw -> B1[n*ldb1 + k], else B2[n*ldb2 + k-ksw]. Tile 128x64x32.
__global__ __launch_bounds__(256) void gemm_kernel(
    const float *__restrict__ A, const __nv_bfloat16 *__restrict__ Ahi,
    const __nv_bfloat16 *__restrict__ Alo, int lda,
    const float *__restrict__ B1, int ldb1, int ksw,
    const float *__restrict__ B2, int ldb2,
    const float *__restrict__ bias1, const float *__restrict__ bias2,
    float *__restrict__ C, int ldc, int K) {
    __shared__ __align__(16) __nv_bfloat16 As_hi[128][40];
    __shared__ __align__(16) __nv_bfloat16 As_lo[128][40];
    __shared__ __align__(16) __nv_bfloat16 Bs_hi[64][40];
    __shared__ __align__(16) __nv_bfloat16 Bs_lo[64][40];

    const int tid = threadIdx.x;
    const int lane = tid & 31;
    const int gid = lane >> 2;
    const int t4 = lane & 3;
    const int wm = (tid >> 5) >> 1;  // 0..3
    const int wn = (tid >> 5) & 1;   // 0..1
    const int m0 = blockIdx.y * 128;
    const int n0 = blockIdx.x * 64;

    float acc[2][4][4];
#pragma unroll
    for (int i = 0; i < 2; i++)
#pragma unroll
        for (int j = 0; j < 4; j++)
#pragma unroll
            for (int c = 0; c < 4; c++) acc[i][j][c] = 0.f;

    for (int k0 = 0; k0 < K; k0 += 32) {
        if (Ahi) {
#pragma unroll
            for (int i = 0; i < 2; ++i) {
                int idx = tid + i * 256;  // uint4 over 512
                int row = idx >> 2;
                int col = (idx & 3) << 3;
                *(uint4 *)&As_hi[row][col] =
                    *(const uint4 *)(Ahi + (size_t)(m0 + row) * lda + k0 + col);
                *(uint4 *)&As_lo[row][col] =
                    *(const uint4 *)(Alo + (size_t)(m0 + row) * lda + k0 + col);
            }
        } else {
#pragma unroll
            for (int i = 0; i < 4; ++i) {
                int idx = tid + i * 256;  // float4 over 1024
                int row = idx >> 3;
                int col = (idx & 7) << 2;
                float4 v4 = *(const float4 *)(A + (size_t)(m0 + row) * lda + k0 + col);
                __nv_bfloat16 h0, h1, h2, h3, l0, l1, l2, l3;
                splitf(v4.x, h0, l0); splitf(v4.y, h1, l1);
                splitf(v4.z, h2, l2); splitf(v4.w, h3, l3);
                *(__nv_bfloat162 *)&As_hi[row][col]     = __halves2bfloat162(h0, h1);
                *(__nv_bfloat162 *)&As_hi[row][col + 2] = __halves2bfloat162(h2, h3);
                *(__nv_bfloat162 *)&As_lo[row][col]     = __halves2bfloat162(l0, l1);
                *(__nv_bfloat162 *)&As_lo[row][col + 2] = __halves2bfloat162(l2, l3);
            }
        }
#pragma unroll
        for (int i = 0; i < 2; ++i) {
            int idx = tid + i * 256;  // float4 over 512
            int row = idx >> 3;
            int col = (idx & 7) << 2;
            int n = n0 + row;
            int k = k0 + col;
            const float *src = (k < ksw) ? (B1 + (size_t)n * ldb1 + k)
                                         : (B2 + (size_t)n * ldb2 + (k - ksw));
            float4 v4 = *(const float4 *)src;
            __nv_bfloat16 h0, h1, h2, h3, l0, l1, l2, l3;
            splitf(v4.x, h0, l0); splitf(v4.y, h1, l1);
            splitf(v4.z, h2, l2); splitf(v4.w, h3, l3);
            *(__nv_bfloat162 *)&Bs_hi[row][col]     = __halves2bfloat162(h0, h1);
            *(__nv_bfloat162 *)&Bs_hi[row][col + 2] = __halves2bfloat162(h2, h3);
            *(__nv_bfloat162 *)&Bs_lo[row][col]     = __halves2bfloat162(l0, l1);
            *(__nv_bfloat162 *)&Bs_lo[row][col + 2] = __halves2bfloat162(l2, l3);
        }
        __syncthreads();
#pragma unroll
        for (int kk = 0; kk < 32; kk += 16) {
            uint32_t ah[2][4], al[2][4];
#pragma unroll
            for (int fm = 0; fm < 2; ++fm)
#pragma unroll
                for (int r = 0; r < 4; ++r) {
                    int row = wm * 32 + fm * 16 + gid + ((r & 1) << 3);
                    int col = kk + (t4 << 1) + ((r >> 1) << 3);
                    ah[fm][r] = *(const uint32_t *)&As_hi[row][col];
                    al[fm][r] = *(const uint32_t *)&As_lo[row][col];
                }
            uint32_t bh[4][2], bl[4][2];
#pragma unroll
            for (int fn = 0; fn < 4; ++fn) {
                int nn = wn * 32 + fn * 8 + gid;
                bh[fn][0] = *(const uint32_t *)&Bs_hi[nn][kk + (t4 << 1)];
                bh[fn][1] = *(const uint32_t *)&Bs_hi[nn][kk + (t4 << 1) + 8];
                bl[fn][0] = *(const uint32_t *)&Bs_lo[nn][kk + (t4 << 1)];
                bl[fn][1] = *(const uint32_t *)&Bs_lo[nn][kk + (t4 << 1) + 8];
            }
#pragma unroll
            for (int fm = 0; fm < 2; ++fm)
#pragma unroll
                for (int fn = 0; fn < 4; ++fn) {
                    MMA16816(acc[fm][fn], ah[fm], bh[fn]);
                    MMA16816(acc[fm][fn], ah[fm], bl[fn]);
                    MMA16816(acc[fm][fn], al[fm], bh[fn]);
                }
        }
        __syncthreads();
    }
#pragma unroll
    for (int fm = 0; fm < 2; ++fm)
#pragma unroll
        for (int fn = 0; fn < 4; ++fn) {
            int row = m0 + wm * 32 + fm * 16 + gid;
            int col = n0 + wn * 32 + fn * 8 + (t4 << 1);
            float b0 = 0.f, b1 = 0.f;
            if (bias1) { b0 += bias1[col]; b1 += bias1[col + 1]; }
            if (bias2) { b0 += bias2[col]; b1 += bias2[col + 1]; }
            C[(size_t)row * ldc + col]           = acc[fm][fn][0] + b0;
            C[(size_t)row * ldc + col + 1]       = acc[fm][fn][1] + b1;
            C[(size_t)(row + 8) * ldc + col]     = acc[fm][fn][2] + b0;
            C[(size_t)(row + 8) * ldc + col + 1] = acc[fm][fn][3] + b1;
        }
}

// ---------------- fused energy GEMM + tanh + v-dot -> score[B,S] -------------
// Block b computes score[b, :] ; rows = s (128), energy features n swept in
// 16 chunks of 64, K = 1024. A = g_enc split, B = g_w2 split. Energy never hits
// global memory.
__global__ __launch_bounds__(256) void attn_score_kernel(const float *__restrict__ v) {
    __shared__ __align__(16) __nv_bfloat16 As_hi[128][40];
    __shared__ __align__(16) __nv_bfloat16 As_lo[128][40];
    __shared__ __align__(16) __nv_bfloat16 Bs_hi[64][40];
    __shared__ __align__(16) __nv_bfloat16 Bs_lo[64][40];
    __shared__ float red[128];

    const int b = blockIdx.x;
    const int tid = threadIdx.x;
    const int lane = tid & 31;
    const int gid = lane >> 2;
    const int t4 = lane & 3;
    const int wm = (tid >> 5) >> 1;
    const int wn = (tid >> 5) & 1;
    if (tid < 128) red[tid] = 0.f;

    const float *hWb = g_hW + (size_t)b * CH;
    float pA[2] = {0.f, 0.f}, pB[2] = {0.f, 0.f};

    for (int nc = 0; nc < 16; ++nc) {
        const int n0 = nc * 64;
        float acc[2][4][4];
#pragma unroll
        for (int i = 0; i < 2; i++)
#pragma unroll
            for (int j = 0; j < 4; j++)
#pragma unroll
                for (int c = 0; c < 4; c++) acc[i][j][c] = 0.f;

        for (int k0 = 0; k0 < CH; k0 += 32) {
#pragma unroll
            for (int i = 0; i < 2; ++i) {
                int idx = tid + i * 256;
                int row = idx >> 2;
                int col = (idx & 3) << 3;
                size_t go = (size_t)(b * 128 + row) * CH + k0 + col;
                *(uint4 *)&As_hi[row][col] = *(const uint4 *)(g_enc_hi + go);
                *(uint4 *)&As_lo[row][col] = *(const uint4 *)(g_enc_lo + go);
            }
            {
                int row = tid >> 2;
                int col = (tid & 3) << 3;
                size_t go = (size_t)(n0 + row) * CH + k0 + col;
                *(uint4 *)&Bs_hi[row][col] = *(const uint4 *)(g_w2_hi + go);
                *(uint4 *)&Bs_lo[row][col] = *(const uint4 *)(g_w2_lo + go);
            }
            __syncthreads();
#pragma unroll
            for (int kk = 0; kk < 32; kk += 16) {
                uint32_t ah[2][4], al[2][4];
#pragma unroll
                for (int fm = 0; fm < 2; ++fm)
#pragma unroll
                    for (int r = 0; r < 4; ++r) {
                        int row = wm * 32 + fm * 16 + gid + ((r & 1) << 3);
                        int col = kk + (t4 << 1) + ((r >> 1) << 3);
                        ah[fm][r] = *(const uint32_t *)&As_hi[row][col];
                        al[fm][r] = *(const uint32_t *)&As_lo[row][col];
                    }
                uint32_t bh[4][2], bl[4][2];
#pragma unroll
                for (int fn = 0; fn < 4; ++fn) {
                    int nn = wn * 32 + fn * 8 + gid;
                    bh[fn][0] = *(const uint32_t *)&Bs_hi[nn][kk + (t4 << 1)];
                    bh[fn][1] = *(const uint32_t *)&Bs_hi[nn][kk + (t4 << 1) + 8];
                    bl[fn][0] = *(const uint32_t *)&Bs_lo[nn][kk + (t4 << 1)];
                    bl[fn][1] = *(const uint32_t *)&Bs_lo[nn][kk + (t4 << 1) + 8];
                }
#pragma unroll
                for (int fm = 0; fm < 2; ++fm)
#pragma unroll
                    for (int fn = 0; fn < 4; ++fn) {
                        MMA16816(acc[fm][fn], ah[fm], bh[fn]);
                        MMA16816(acc[fm][fn], ah[fm], bl[fn]);
                        MMA16816(acc[fm][fn], al[fm], bh[fn]);
                    }
            }
            __syncthreads();
        }
        // epilogue for this n-chunk: tanh(energy + hW) * v, accumulate per row
#pragma unroll
        for (int fm = 0; fm < 2; ++fm)
#pragma unroll
            for (int fn = 0; fn < 4; ++fn) {
                int col = n0 + wn * 32 + fn * 8 + (t4 << 1);
                float hw0 = hWb[col], hw1 = hWb[col + 1];
                float v0 = v[col], v1 = v[col + 1];
                pA[fm] += tanhf(acc[fm][fn][0] + hw0) * v0 +
                          tanhf(acc[fm][fn][1] + hw1) * v1;
                pB[fm] += tanhf(acc[fm][fn][2] + hw0) * v0 +
                          tanhf(acc[fm][fn][3] + hw1) * v1;
            }
    }
#pragma unroll
    for (int fm = 0; fm < 2; ++fm)
#pragma unroll
        for (int j = 0; j < 2; ++j) {
            float val = j ? pB[fm] : pA[fm];
            val += __shfl_xor_sync(0xffffffffu, val, 1);
            val += __shfl_xor_sync(0xffffffffu, val, 2);
            if (t4 == 0) atomicAdd(&red[wm * 32 + fm * 16 + j * 8 + gid], val);
        }
    __syncthreads();
    if (tid < 128) g_score[b * 128 + tid] = red[tid];
}

// ---------------- softmax over S, writes attn output + weights in place ------
__global__ __launch_bounds__(128) void softmax_kernel(float *__restrict__ out_attn) {
    const int b = blockIdx.x;
    const int t = threadIdx.x;
    __shared__ float sm[128];
    float s = g_score[b * 128 + t];
    sm[t] = s;
    __syncthreads();
#pragma unroll
    for (int st = 64; st > 0; st >>= 1) {
        if (t < st) sm[t] = fmaxf(sm[t], sm[t + st]);
        __syncthreads();
    }
    float mx = sm[0];
    __syncthreads();
    float e = expf(s - mx);
    sm[t] = e;
    __syncthreads();
#pragma unroll
    for (int st = 64; st > 0; st >>= 1) {
        if (t < st) sm[t] += sm[t + st];
        __syncthreads();
    }
    float w = e / sm[0];
    g_score[b * 128 + t] = w;
    out_attn[b * 128 + t] = w;
}

// ---------------- context + assemble xin (emb|context|h_last) ----------------
__global__ __launch_bounds__(256) void context_kernel(
    const int *__restrict__ x, const float *__restrict__ emb_table,
    const float *__restrict__ hidden, const float *__restrict__ enc) {
    const int b = blockIdx.x;
    const int t = threadIdx.x;
    __shared__ float w_s[128];
    if (t < 128) w_s[t] = g_score[b * 128 + t];
    int tok = x[b];
    for (int i = t; i < CE; i += 256)
        g_xin[(size_t)b * 2560 + i] = emb_table[(size_t)tok * CE + i];
    for (int i = t; i < CH; i += 256)
        g_xin[(size_t)b * 2560 + 1536 + i] = hidden[(size_t)b * CH + i];
    __syncthreads();
    float acc[4] = {0.f, 0.f, 0.f, 0.f};
    const float *encb = enc + (size_t)b * CS * CH;
    for (int s = 0; s < CS; ++s) {
        float w = w_s[s];
        const float *er = encb + (size_t)s * CH;
#pragma unroll
        for (int i = 0; i < 4; ++i) acc[i] += w * er[t + i * 256];
    }
#pragma unroll
    for (int i = 0; i < 4; ++i) {
        int h = t + i * 256;
        float c = acc[i];
        g_xin[(size_t)b * 2560 + 512 + h] = c;
        __nv_bfloat16 hi, lo;
        splitf(c, hi, lo);
        g_out2_hi[(size_t)b * 2048 + 1024 + h] = hi;
        g_out2_lo[(size_t)b * 2048 + 1024 + h] = lo;
    }
}

// ---------------- LSTM pointwise ---------------------------------------------
__global__ __launch_bounds__(256) void lstm_kernel(
    const float *__restrict__ cell, float *__restrict__ out_h,
    float *__restrict__ out_c) {
    int id = blockIdx.x * 256 + threadIdx.x;  // 131072
    int b = id >> 10;
    int h = id & 1023;
    const float *gt = g_gates + (size_t)b * 4096;
    float gi = gt[h], gf = gt[1024 + h], gg = gt[2048 + h], go = gt[3072 + h];
    float c_old = cell[(size_t)b * CH + h];
    float cn = sigf(gf) * c_old + sigf(gi) * tanhf(gg);
    float hn = sigf(go) * tanhf(cn);
    out_h[(size_t)b * CH + h] = hn;
    out_c[(size_t)b * CH + h] = cn;
    __nv_bfloat16 hi, lo;
    splitf(hn, hi, lo);
    g_out2_hi[(size_t)b * 2048 + h] = hi;
    g_out2_lo[(size_t)b * 2048 + h] = lo;
}

// ---------------- launch ------------------------------------------------------
extern "C" void kernel_launch(void *const *d_in, const int *in_sizes, int n_in,
                              void *d_out, int out_size) {
    (void)in_sizes; (void)n_in; (void)out_size;
    const int *x           = (const int *)d_in[0];
    const float *hidden    = (const float *)d_in[1];
    const float *cell      = (const float *)d_in[2];
    const float *enc       = (const float *)d_in[3];
    const float *emb_table = (const float *)d_in[4];
    const float *attn_W    = (const float *)d_in[5];
    const float *attn_b    = (const float *)d_in[6];
    const float *v         = (const float *)d_in[7];
    const float *W_ih      = (const float *)d_in[8];
    const float *W_hh      = (const float *)d_in[9];
    const float *b_ih      = (const float *)d_in[10];
    const float *b_hh      = (const float *)d_in[11];
    const float *fc_W      = (const float *)d_in[12];
    const float *fc_b      = (const float *)d_in[13];

    float *out        = (float *)d_out;
    float *out_logits = out;
    float *out_h      = out + (size_t)CB * CV;
    float *out_c      = out_h + (size_t)CB * CH;
    float *out_attn   = out_c + (size_t)CB * CH;

    float *hWp = nullptr, *xinp = nullptr, *gatesp = nullptr;
    __nv_bfloat16 *o2h = nullptr, *o2l = nullptr;
    cudaGetSymbolAddress((void **)&hWp, g_hW);
    cudaGetSymbolAddress((void **)&xinp, g_xin);
    cudaGetSymbolAddress((void **)&gatesp, g_gates);
    cudaGetSymbolAddress((void **)&o2h, g_out2_hi);
    cudaGetSymbolAddress((void **)&o2l, g_out2_lo);

    // 1) precision-split encoder_outputs and attn_W[:, H:2H]
    conv_enc_kernel<<<16384, 256>>>(enc);
    conv_w2_kernel<<<1024, 256>>>(attn_W);

    // 2) hW = h_last @ attn_W[:, :H]^T + attn_b   -> g_hW [B,H]
    gemm_kernel<<<dim3(CH / 64, 1), 256>>>(
        hidden, nullptr, nullptr, CH,
        attn_W, 2 * CH, CH, nullptr, 0,
        attn_b, nullptr, hWp, CH, CH);

    // 3) fused energy GEMM + tanh + v-dot -> g_score [B,S]
    attn_score_kernel<<<CB, 256>>>(v);

    // 4) softmax -> attn_weights (output) + g_score in place
    softmax_kernel<<<CB, 128>>>(out_attn);

    // 5) context = w @ enc ; assemble xin = [emb|context|h_last], out2 ctx half
    context_kernel<<<CB, 256>>>(x, emb_table, hidden, enc);

    // 6) gates = xin @ [W_ih|W_hh]^T + b_ih + b_hh   (K = 1536 + 1024)
    gemm_kernel<<<dim3(4096 / 64, 1), 256>>>(
        xinp, nullptr, nullptr, 2560,
        W_ih, 1536, 1536, W_hh, CH,
        b_ih, b_hh, gatesp, 4096, 2560);

    // 7) LSTM pointwise -> h_new, c_new outputs + out2 h half (bf16 split)
    lstm_kernel<<<(CB * CH) / 256, 256>>>(cell, out_h, out_c);

    // 8) logits = [h_new|context] @ fc_W^T + fc_b
    gemm_kernel<<<dim3(CV / 64, 1), 256>>>(
        nullptr, o2h, o2l, 2048,
        fc_W, 2048, 2048, nullptr, 0,
        fc_b, nullptr, out_logits, CV, 2048);
}

// round 2
// speedup vs baseline: 1.2694x; 1.2694x over previous
#include <cuda_runtime.h>
#include <cuda_bf16.h>
#include <stdint.h>
#include <math.h>

#define CB 128
#define CS 128
#define CH 1024
#define CE 512
#define CV 32000

// ---------------- scratch (__device__ globals; no allocations allowed) -------
__device__ __align__(16) float g_hW[CB * CH];
__device__ __align__(16) float g_score[CB * CS];
__device__ __align__(16) float g_xin[CB * 2560];      // [emb(512)|context(1024)|h_last(1024)]
__device__ __align__(16) float g_gates[CB * 4096];
__device__ __align__(16) __nv_bfloat16 g_out2_hi[CB * 2048];  // [h_new | context]
__device__ __align__(16) __nv_bfloat16 g_out2_lo[CB * 2048];
__device__ __align__(16) __nv_bfloat16 g_enc_hi[CB * CS * CH];
__device__ __align__(16) __nv_bfloat16 g_enc_lo[CB * CS * CH];
__device__ __align__(16) __nv_bfloat16 g_w2_hi[CH * CH];      // attn_W[:, H:2H] as [n][k]
__device__ __align__(16) __nv_bfloat16 g_w2_lo[CH * CH];

// ---------------- helpers ----------------------------------------------------
__device__ __forceinline__ void splitf(float x, __nv_bfloat16 &hi, __nv_bfloat16 &lo) {
    hi = __float2bfloat16_rn(x);
    lo = __float2bfloat16_rn(x - __bfloat162float(hi));
}
__device__ __forceinline__ float sigf(float x) { return 1.0f / (1.0f + expf(-x)); }
__device__ __forceinline__ uint32_t s2u(const void *p) {
    return (uint32_t)__cvta_generic_to_shared(p);
}

#define MMA16816(d, a, b)                                                      \
    asm volatile(                                                              \
        "mma.sync.aligned.m16n8k16.row.col.f32.bf16.bf16.f32 "                 \
        "{%0,%1,%2,%3},{%4,%5,%6,%7},{%8,%9},{%0,%1,%2,%3};\n"                 \
        : "+f"(d[0]), "+f"(d[1]), "+f"(d[2]), "+f"(d[3])                       \
        : "r"(a[0]), "r"(a[1]), "r"(a[2]), "r"(a[3]), "r"(b[0]), "r"(b[1]))

#define CPASYNC16(dst, src)                                                    \
    asm volatile("cp.async.cg.shared.global [%0], [%1], 16;\n" ::"r"(dst),     \
                 "l"(src))
#define CPCOMMIT asm volatile("cp.async.commit_group;\n" ::)
#define CPWAIT1 asm volatile("cp.async.wait_group 1;\n" ::)
#define CPWAIT0 asm volatile("cp.async.wait_group 0;\n" ::)

// ---------------- zero score accumulator -------------------------------------
__global__ __launch_bounds__(256) void zero_score_kernel() {
    g_score[blockIdx.x * 256 + threadIdx.x] = 0.f;
}

// ---------------- precision split of encoder_outputs and attn_W[:,H:] --------
__global__ __launch_bounds__(256) void conv_enc_kernel(const float *__restrict__ enc) {
    size_t idx = (size_t)blockIdx.x * 256 + threadIdx.x;  // float4 index
    float4 v4 = ((const float4 *)enc)[idx];
    __nv_bfloat16 h0, h1, h2, h3, l0, l1, l2, l3;
    splitf(v4.x, h0, l0); splitf(v4.y, h1, l1);
    splitf(v4.z, h2, l2); splitf(v4.w, h3, l3);
    ((__nv_bfloat162 *)g_enc_hi)[idx * 2 + 0] = __halves2bfloat162(h0, h1);
    ((__nv_bfloat162 *)g_enc_hi)[idx * 2 + 1] = __halves2bfloat162(h2, h3);
    ((__nv_bfloat162 *)g_enc_lo)[idx * 2 + 0] = __halves2bfloat162(l0, l1);
    ((__nv_bfloat162 *)g_enc_lo)[idx * 2 + 1] = __halves2bfloat162(l2, l3);
}

__global__ __launch_bounds__(256) void conv_w2_kernel(const float *__restrict__ attn_W) {
    size_t idx = (size_t)blockIdx.x * 256 + threadIdx.x;  // float4 index, 262144 total
    int n = (int)(idx >> 8);
    int k = (int)(idx & 255) << 2;
    float4 v4 = *(const float4 *)(attn_W + (size_t)n * 2048 + 1024 + k);
    __nv_bfloat16 h0, h1, h2, h3, l0, l1, l2, l3;
    splitf(v4.x, h0, l0); splitf(v4.y, h1, l1);
    splitf(v4.z, h2, l2); splitf(v4.w, h3, l3);
    size_t o = ((size_t)n * CH + k) >> 1;
    ((__nv_bfloat162 *)g_w2_hi)[o + 0] = __halves2bfloat162(h0, h1);
    ((__nv_bfloat162 *)g_w2_hi)[o + 1] = __halves2bfloat162(h2, h3);
    ((__nv_bfloat162 *)g_w2_lo)[o + 0] = __halves2bfloat162(l0, l1);
    ((__nv_bfloat162 *)g_w2_lo)[o + 1] = __halves2bfloat162(l2, l3);
}

// ---------------- generic bf16-split x3 GEMM: C[M,N] = A@B^T (+bias) ---------
__global__ __launch_bounds__(256) void gemm_kernel(
    const float *__restrict__ A, const __nv_bfloat16 *__restrict__ Ahi,
    const __nv_bfloat16 *__restrict__ Alo, int lda,
    const float *__restrict__ B1, int ldb1, int ksw,
    const float *__restrict__ B2, int ldb2,
    const float *__restrict__ bias1, const float *__restrict__ bias2,
    float *__restrict__ C, int ldc, int K) {
    __shared__ __align__(16) __nv_bfloat16 As_hi[128][40];
    __shared__ __align__(16) __nv_bfloat16 As_lo[128][40];
    __shared__ __align__(16) __nv_bfloat16 Bs_hi[64][40];
    __shared__ __align__(16) __nv_bfloat16 Bs_lo[64][40];

    const int tid = threadIdx.x;
    const int lane = tid & 31;
    const int gid = lane >> 2;
    const int t4 = lane & 3;
    const int wm = (tid >> 5) >> 1;  // 0..3
    const int wn = (tid >> 5) & 1;   // 0..1
    const int m0 = blockIdx.y * 128;
    const int n0 = blockIdx.x * 64;

    float acc[2][4][4];
#pragma unroll
    for (int i = 0; i < 2; i++)
#pragma unroll
        for (int j = 0; j < 4; j++)
#pragma unroll
            for (int c = 0; c < 4; c++) acc[i][j][c] = 0.f;

    for (int k0 = 0; k0 < K; k0 += 32) {
        if (Ahi) {
#pragma unroll
            for (int i = 0; i < 2; ++i) {
                int idx = tid + i * 256;  // uint4 over 512
                int row = idx >> 2;
                int col = (idx & 3) << 3;
                *(uint4 *)&As_hi[row][col] =
                    *(const uint4 *)(Ahi + (size_t)(m0 + row) * lda + k0 + col);
                *(uint4 *)&As_lo[row][col] =
                    *(const uint4 *)(Alo + (size_t)(m0 + row) * lda + k0 + col);
            }
        } else {
#pragma unroll
            for (int i = 0; i < 4; ++i) {
                int idx = tid + i * 256;  // float4 over 1024
                int row = idx >> 3;
                int col = (idx & 7) << 2;
                float4 v4 = *(const float4 *)(A + (size_t)(m0 + row) * lda + k0 + col);
                __nv_bfloat16 h0, h1, h2, h3, l0, l1, l2, l3;
                splitf(v4.x, h0, l0); splitf(v4.y, h1, l1);
                splitf(v4.z, h2, l2); splitf(v4.w, h3, l3);
                *(__nv_bfloat162 *)&As_hi[row][col]     = __halves2bfloat162(h0, h1);
                *(__nv_bfloat162 *)&As_hi[row][col + 2] = __halves2bfloat162(h2, h3);
                *(__nv_bfloat162 *)&As_lo[row][col]     = __halves2bfloat162(l0, l1);
                *(__nv_bfloat162 *)&As_lo[row][col + 2] = __halves2bfloat162(l2, l3);
            }
        }
#pragma unroll
        for (int i = 0; i < 2; ++i) {
            int idx = tid + i * 256;  // float4 over 512
            int row = idx >> 3;
            int col = (idx & 7) << 2;
            int n = n0 + row;
            int k = k0 + col;
            const float *src = (k < ksw) ? (B1 + (size_t)n * ldb1 + k)
                                         : (B2 + (size_t)n * ldb2 + (k - ksw));
            float4 v4 = *(const float4 *)src;
            __nv_bfloat16 h0, h1, h2, h3, l0, l1, l2, l3;
            splitf(v4.x, h0, l0); splitf(v4.y, h1, l1);
            splitf(v4.z, h2, l2); splitf(v4.w, h3, l3);
            *(__nv_bfloat162 *)&Bs_hi[row][col]     = __halves2bfloat162(h0, h1);
            *(__nv_bfloat162 *)&Bs_hi[row][col + 2] = __halves2bfloat162(h2, h3);
            *(__nv_bfloat162 *)&Bs_lo[row][col]     = __halves2bfloat162(l0, l1);
            *(__nv_bfloat162 *)&Bs_lo[row][col + 2] = __halves2bfloat162(l2, l3);
        }
        __syncthreads();
#pragma unroll
        for (int kk = 0; kk < 32; kk += 16) {
            uint32_t ah[2][4], al[2][4];
#pragma unroll
            for (int fm = 0; fm < 2; ++fm)
#pragma unroll
                for (int r = 0; r < 4; ++r) {
                    int row = wm * 32 + fm * 16 + gid + ((r & 1) << 3);
                    int col = kk + (t4 << 1) + ((r >> 1) << 3);
                    ah[fm][r] = *(const uint32_t *)&As_hi[row][col];
                    al[fm][r] = *(const uint32_t *)&As_lo[row][col];
                }
            uint32_t bh[4][2], bl[4][2];
#pragma unroll
            for (int fn = 0; fn < 4; ++fn) {
                int nn = wn * 32 + fn * 8 + gid;
                bh[fn][0] = *(const uint32_t *)&Bs_hi[nn][kk + (t4 << 1)];
                bh[fn][1] = *(const uint32_t *)&Bs_hi[nn][kk + (t4 << 1) + 8];
                bl[fn][0] = *(const uint32_t *)&Bs_lo[nn][kk + (t4 << 1)];
                bl[fn][1] = *(const uint32_t *)&Bs_lo[nn][kk + (t4 << 1) + 8];
            }
#pragma unroll
            for (int fm = 0; fm < 2; ++fm)
#pragma unroll
                for (int fn = 0; fn < 4; ++fn) {
                    MMA16816(acc[fm][fn], ah[fm], bh[fn]);
                    MMA16816(acc[fm][fn], ah[fm], bl[fn]);
                    MMA16816(acc[fm][fn], al[fm], bh[fn]);
                }
        }
        __syncthreads();
    }
#pragma unroll
    for (int fm = 0; fm < 2; ++fm)
#pragma unroll
        for (int fn = 0; fn < 4; ++fn) {
            int row = m0 + wm * 32 + fm * 16 + gid;
            int col = n0 + wn * 32 + fn * 8 + (t4 << 1);
            float b0 = 0.f, b1 = 0.f;
            if (bias1) { b0 += bias1[col]; b1 += bias1[col + 1]; }
            if (bias2) { b0 += bias2[col]; b1 += bias2[col + 1]; }
            C[(size_t)row * ldc + col]           = acc[fm][fn][0] + b0;
            C[(size_t)row * ldc + col + 1]       = acc[fm][fn][1] + b1;
            C[(size_t)(row + 8) * ldc + col]     = acc[fm][fn][2] + b0;
            C[(size_t)(row + 8) * ldc + col + 1] = acc[fm][fn][3] + b1;
        }
}

// ---------------- fused energy GEMM + tanh + v-dot -> score[B,S] -------------
// Grid (16, 128): blockIdx.y = batch b, blockIdx.x = n-chunk (64 cols of H).
// Each CTA: GEMM 128x64x1024 (bf16 split x3), epilogue tanh+v-dot partial sum,
// atomicAdd into g_score[b, :]. cp.async 2-stage double buffered, dynamic smem.
// smem layout (bf16 elems): AsHi[2][128*40] | AsLo[2][128*40] |
//                           BsHi[2][64*40]  | BsLo[2][64*40]  | red[128] floats
#define AS_STRIDE 40
#define AS_STAGE (128 * AS_STRIDE)
#define BS_STAGE (64 * AS_STRIDE)
#define ATTN_SMEM_BYTES ((2 * AS_STAGE * 2 + 2 * BS_STAGE * 2) * 2 + 128 * 4)

__global__ __launch_bounds__(256, 2) void attn_score_kernel(const float *__restrict__ v) {
    extern __shared__ __align__(16) __nv_bfloat16 smem[];
    __nv_bfloat16 *AsHi = smem;
    __nv_bfloat16 *AsLo = AsHi + 2 * AS_STAGE;
    __nv_bfloat16 *BsHi = AsLo + 2 * AS_STAGE;
    __nv_bfloat16 *BsLo = BsHi + 2 * BS_STAGE;
    float *red = (float *)(BsLo + 2 * BS_STAGE);

    const int b = blockIdx.y;
    const int n0 = blockIdx.x * 64;
    const int tid = threadIdx.x;
    const int lane = tid & 31;
    const int gid = lane >> 2;
    const int t4 = lane & 3;
    const int wm = (tid >> 5) >> 1;
    const int wn = (tid >> 5) & 1;
    if (tid < 128) red[tid] = 0.f;

    // precompute cp.async src/dst for this thread
    const int a_row0 = tid >> 2;            // rows 0..63   (i=0)
    const int a_col = (tid & 3) << 3;       // 0,8,16,24
    const int b_row = tid >> 2;
    const int b_col = (tid & 3) << 3;

    float acc[2][4][4];
#pragma unroll
    for (int i = 0; i < 2; i++)
#pragma unroll
        for (int j = 0; j < 4; j++)
#pragma unroll
            for (int c = 0; c < 4; c++) acc[i][j][c] = 0.f;

#define LOAD_STAGE(st, k0)                                                     \
    do {                                                                       \
        _Pragma("unroll") for (int i = 0; i < 2; ++i) {                        \
            int row = a_row0 + i * 64;                                         \
            size_t go = (size_t)(b * 128 + row) * CH + (k0) + a_col;           \
            uint32_t dof = (st) * AS_STAGE + row * AS_STRIDE + a_col;          \
            CPASYNC16(s2u(AsHi + dof), g_enc_hi + go);                         \
            CPASYNC16(s2u(AsLo + dof), g_enc_lo + go);                         \
        }                                                                      \
        {                                                                      \
            size_t go = (size_t)(n0 + b_row) * CH + (k0) + b_col;              \
            uint32_t dof = (st) * BS_STAGE + b_row * AS_STRIDE + b_col;        \
            CPASYNC16(s2u(BsHi + dof), g_w2_hi + go);                          \
            CPASYNC16(s2u(BsLo + dof), g_w2_lo + go);                          \
        }                                                                      \
        CPCOMMIT;                                                              \
    } while (0)

    LOAD_STAGE(0, 0);
    for (int kt = 0; kt < 32; ++kt) {
        if (kt + 1 < 32) {
            LOAD_STAGE((kt + 1) & 1, (kt + 1) * 32);
            CPWAIT1;
        } else {
            CPWAIT0;
        }
        __syncthreads();
        const int cur = kt & 1;
        const __nv_bfloat16 *cAH = AsHi + cur * AS_STAGE;
        const __nv_bfloat16 *cAL = AsLo + cur * AS_STAGE;
        const __nv_bfloat16 *cBH = BsHi + cur * BS_STAGE;
        const __nv_bfloat16 *cBL = BsLo + cur * BS_STAGE;
#pragma unroll
        for (int kk = 0; kk < 32; kk += 16) {
            uint32_t ah[2][4], al[2][4];
#pragma unroll
            for (int fm = 0; fm < 2; ++fm)
#pragma unroll
                for (int r = 0; r < 4; ++r) {
                    int row = wm * 32 + fm * 16 + gid + ((r & 1) << 3);
                    int col = kk + (t4 << 1) + ((r >> 1) << 3);
                    ah[fm][r] = *(const uint32_t *)(cAH + row * AS_STRIDE + col);
                    al[fm][r] = *(const uint32_t *)(cAL + row * AS_STRIDE + col);
                }
            uint32_t bh[4][2], bl[4][2];
#pragma unroll
            for (int fn = 0; fn < 4; ++fn) {
                int nn = wn * 32 + fn * 8 + gid;
                bh[fn][0] = *(const uint32_t *)(cBH + nn * AS_STRIDE + kk + (t4 << 1));
                bh[fn][1] = *(const uint32_t *)(cBH + nn * AS_STRIDE + kk + (t4 << 1) + 8);
                bl[fn][0] = *(const uint32_t *)(cBL + nn * AS_STRIDE + kk + (t4 << 1));
                bl[fn][1] = *(const uint32_t *)(cBL + nn * AS_STRIDE + kk + (t4 << 1) + 8);
            }
#pragma unroll
            for (int fm = 0; fm < 2; ++fm)
#pragma unroll
                for (int fn = 0; fn < 4; ++fn) {
                    MMA16816(acc[fm][fn], ah[fm], bh[fn]);
                    MMA16816(acc[fm][fn], ah[fm], bl[fn]);
                    MMA16816(acc[fm][fn], al[fm], bh[fn]);
                }
        }
        __syncthreads();
    }

    // epilogue: tanh(energy + hW) * v, partial per-row sums
    const float *hWb = g_hW + (size_t)b * CH;
    float pA[2] = {0.f, 0.f}, pB[2] = {0.f, 0.f};
#pragma unroll
    for (int fm = 0; fm < 2; ++fm)
#pragma unroll
        for (int fn = 0; fn < 4; ++fn) {
            int col = n0 + wn * 32 + fn * 8 + (t4 << 1);
            float hw0 = hWb[col], hw1 = hWb[col + 1];
            float v0 = v[col], v1 = v[col + 1];
            pA[fm] += tanhf(acc[fm][fn][0] + hw0) * v0 +
                      tanhf(acc[fm][fn][1] + hw1) * v1;
            pB[fm] += tanhf(acc[fm][fn][2] + hw0) * v0 +
                      tanhf(acc[fm][fn][3] + hw1) * v1;
        }
#pragma unroll
    for (int fm = 0; fm < 2; ++fm)
#pragma unroll
        for (int j = 0; j < 2; ++j) {
            float val = j ? pB[fm] : pA[fm];
            val += __shfl_xor_sync(0xffffffffu, val, 1);
            val += __shfl_xor_sync(0xffffffffu, val, 2);
            if (t4 == 0) atomicAdd(&red[wm * 32 + fm * 16 + j * 8 + gid], val);
        }
    __syncthreads();
    if (tid < 128) atomicAdd(&g_score[b * 128 + tid], red[tid]);
}

// ---------------- softmax over S, writes attn output + weights in place ------
__global__ __launch_bounds__(128) void softmax_kernel(float *__restrict__ out_attn) {
    const int b = blockIdx.x;
    const int t = threadIdx.x;
    __shared__ float sm[128];
    float s = g_score[b * 128 + t];
    sm[t] = s;
    __syncthreads();
#pragma unroll
    for (int st = 64; st > 0; st >>= 1) {
        if (t < st) sm[t] = fmaxf(sm[t], sm[t + st]);
        __syncthreads();
    }
    float mx = sm[0];
    __syncthreads();
    float e = expf(s - mx);
    sm[t] = e;
    __syncthreads();
#pragma unroll
    for (int st = 64; st > 0; st >>= 1) {
        if (t < st) sm[t] += sm[t + st];
        __syncthreads();
    }
    float w = e / sm[0];
    g_score[b * 128 + t] = w;
    out_attn[b * 128 + t] = w;
}

// ---------------- context + assemble xin (emb|context|h_last) ----------------
__global__ __launch_bounds__(256) void context_kernel(
    const int *__restrict__ x, const float *__restrict__ emb_table,
    const float *__restrict__ hidden, const float *__restrict__ enc) {
    const int b = blockIdx.x;
    const int t = threadIdx.x;
    __shared__ float w_s[128];
    if (t < 128) w_s[t] = g_score[b * 128 + t];
    int tok = x[b];
    for (int i = t; i < CE; i += 256)
        g_xin[(size_t)b * 2560 + i] = emb_table[(size_t)tok * CE + i];
    for (int i = t; i < CH; i += 256)
        g_xin[(size_t)b * 2560 + 1536 + i] = hidden[(size_t)b * CH + i];
    __syncthreads();
    float acc[4] = {0.f, 0.f, 0.f, 0.f};
    const float *encb = enc + (size_t)b * CS * CH;
    for (int s = 0; s < CS; ++s) {
        float w = w_s[s];
        const float *er = encb + (size_t)s * CH;
#pragma unroll
        for (int i = 0; i < 4; ++i) acc[i] += w * er[t + i * 256];
    }
#pragma unroll
    for (int i = 0; i < 4; ++i) {
        int h = t + i * 256;
        float c = acc[i];
        g_xin[(size_t)b * 2560 + 512 + h] = c;
        __nv_bfloat16 hi, lo;
        splitf(c, hi, lo);
        g_out2_hi[(size_t)b * 2048 + 1024 + h] = hi;
        g_out2_lo[(size_t)b * 2048 + 1024 + h] = lo;
    }
}

// ---------------- LSTM pointwise ---------------------------------------------
__global__ __launch_bounds__(256) void lstm_kernel(
    const float *__restrict__ cell, float *__restrict__ out_h,
    float *__restrict__ out_c) {
    int id = blockIdx.x * 256 + threadIdx.x;  // 131072
    int b = id >> 10;
    int h = id & 1023;
    const float *gt = g_gates + (size_t)b * 4096;
    float gi = gt[h], gf = gt[1024 + h], gg = gt[2048 + h], go = gt[3072 + h];
    float c_old = cell[(size_t)b * CH + h];
    float cn = sigf(gf) * c_old + sigf(gi) * tanhf(gg);
    float hn = sigf(go) * tanhf(cn);
    out_h[(size_t)b * CH + h] = hn;
    out_c[(size_t)b * CH + h] = cn;
    __nv_bfloat16 hi, lo;
    splitf(hn, hi, lo);
    g_out2_hi[(size_t)b * 2048 + h] = hi;
    g_out2_lo[(size_t)b * 2048 + h] = lo;
}

// ---------------- launch ------------------------------------------------------
extern "C" void kernel_launch(void *const *d_in, const int *in_sizes, int n_in,
                              void *d_out, int out_size) {
    (void)in_sizes; (void)n_in; (void)out_size;
    const int *x           = (const int *)d_in[0];
    const float *hidden    = (const float *)d_in[1];
    const float *cell      = (const float *)d_in[2];
    const float *enc       = (const float *)d_in[3];
    const float *emb_table = (const float *)d_in[4];
    const float *attn_W    = (const float *)d_in[5];
    const float *attn_b    = (const float *)d_in[6];
    const float *v         = (const float *)d_in[7];
    const float *W_ih      = (const float *)d_in[8];
    const float *W_hh      = (const float *)d_in[9];
    const float *b_ih      = (const float *)d_in[10];
    const float *b_hh      = (const float *)d_in[11];
    const float *fc_W      = (const float *)d_in[12];
    const float *fc_b      = (const float *)d_in[13];

    float *out        = (float *)d_out;
    float *out_logits = out;
    float *out_h      = out + (size_t)CB * CV;
    float *out_c      = out_h + (size_t)CB * CH;
    float *out_attn   = out_c + (size_t)CB * CH;

    float *hWp = nullptr, *xinp = nullptr, *gatesp = nullptr;
    __nv_bfloat16 *o2h = nullptr, *o2l = nullptr;
    cudaGetSymbolAddress((void **)&hWp, g_hW);
    cudaGetSymbolAddress((void **)&xinp, g_xin);
    cudaGetSymbolAddress((void **)&gatesp, g_gates);
    cudaGetSymbolAddress((void **)&o2h, g_out2_hi);
    cudaGetSymbolAddress((void **)&o2l, g_out2_lo);

    cudaFuncSetAttribute(attn_score_kernel,
                         cudaFuncAttributeMaxDynamicSharedMemorySize,
                         ATTN_SMEM_BYTES);

    // 0) zero the score accumulator
    zero_score_kernel<<<64, 256>>>();

    // 1) precision-split encoder_outputs and attn_W[:, H:2H]
    conv_enc_kernel<<<16384, 256>>>(enc);
    conv_w2_kernel<<<1024, 256>>>(attn_W);

    // 2) hW = h_last @ attn_W[:, :H]^T + attn_b   -> g_hW [B,H]
    gemm_kernel<<<dim3(CH / 64, 1), 256>>>(
        hidden, nullptr, nullptr, CH,
        attn_W, 2 * CH, CH, nullptr, 0,
        attn_b, nullptr, hWp, CH, CH);

    // 3) fused energy GEMM + tanh + v-dot -> g_score [B,S]  (split over n-chunks)
    attn_score_kernel<<<dim3(16, CB), 256, ATTN_SMEM_BYTES>>>(v);

    // 4) softmax -> attn_weights (output) + g_score in place
    softmax_kernel<<<CB, 128>>>(out_attn);

    // 5) context = w @ enc ; assemble xin = [emb|context|h_last], out2 ctx half
    context_kernel<<<CB, 256>>>(x, emb_table, hidden, enc);

    // 6) gates = xin @ [W_ih|W_hh]^T + b_ih + b_hh   (K = 1536 + 1024)
    gemm_kernel<<<dim3(4096 / 64, 1), 256>>>(
        xinp, nullptr, nullptr, 2560,
        W_ih, 1536, 1536, W_hh, CH,
        b_ih, b_hh, gatesp, 4096, 2560);

    // 7) LSTM pointwise -> h_new, c_new outputs + out2 h half (bf16 split)
    lstm_kernel<<<(CB * CH) / 256, 256>>>(cell, out_h, out_c);

    // 8) logits = [h_new|context] @ fc_W^T + fc_b
    gemm_kernel<<<dim3(CV / 64, 1), 256>>>(
        nullptr, o2h, o2l, 2048,
        fc_W, 2048, 2048, nullptr, 0,
        fc_b, nullptr, out_logits, CV, 2048);
}

// round 3
// speedup vs baseline: 1.3463x; 1.0606x over previous
#include <cuda_runtime.h>
#include <cuda_bf16.h>
#include <stdint.h>
#include <math.h>

#define CB 128
#define CS 128
#define CH 1024
#define CE 512
#define CV 32000

// ---------------- scratch (__device__ globals; no allocations allowed) -------
__device__ __align__(16) float g_hW[CB * CH];
__device__ __align__(16) float g_score[CB * CS];
__device__ __align__(16) float g_xin[CB * 2560];      // [emb(512)|context(1024)|h_last(1024)]
__device__ __align__(16) float g_gates[CB * 4096];
__device__ __align__(16) __nv_bfloat16 g_out2_hi[CB * 2048];  // [h_new | context]
__device__ __align__(16) __nv_bfloat16 g_out2_lo[CB * 2048];
__device__ __align__(16) __nv_bfloat16 g_enc_hi[CB * CS * CH];
__device__ __align__(16) __nv_bfloat16 g_enc_lo[CB * CS * CH];
__device__ __align__(16) __nv_bfloat16 g_w2_hi[CH * CH];      // attn_W[:, H:2H] as [n][k]
__device__ __align__(16) __nv_bfloat16 g_w2_lo[CH * CH];

// ---------------- helpers ----------------------------------------------------
__device__ __forceinline__ void splitf(float x, __nv_bfloat16 &hi, __nv_bfloat16 &lo) {
    hi = __float2bfloat16_rn(x);
    lo = __float2bfloat16_rn(x - __bfloat162float(hi));
}
__device__ __forceinline__ float sigf(float x) { return 1.0f / (1.0f + expf(-x)); }
__device__ __forceinline__ uint32_t s2u(const void *p) {
    return (uint32_t)__cvta_generic_to_shared(p);
}
__device__ __forceinline__ void ldsm4(uint32_t &r0, uint32_t &r1, uint32_t &r2,
                                      uint32_t &r3, uint32_t addr) {
    asm volatile("ldmatrix.sync.aligned.m8n8.x4.shared.b16 {%0,%1,%2,%3}, [%4];"
                 : "=r"(r0), "=r"(r1), "=r"(r2), "=r"(r3)
                 : "r"(addr));
}

#define MMA16816(d, a0, a1, a2, a3, b0, b1)                                    \
    asm volatile(                                                              \
        "mma.sync.aligned.m16n8k16.row.col.f32.bf16.bf16.f32 "                 \
        "{%0,%1,%2,%3},{%4,%5,%6,%7},{%8,%9},{%0,%1,%2,%3};\n"                 \
        : "+f"(d[0]), "+f"(d[1]), "+f"(d[2]), "+f"(d[3])                       \
        : "r"(a0), "r"(a1), "r"(a2), "r"(a3), "r"(b0), "r"(b1))

#define CPASYNC16(dst, src)                                                    \
    asm volatile("cp.async.cg.shared.global [%0], [%1], 16;\n" ::"r"(dst),     \
                 "l"(src))
#define CPCOMMIT asm volatile("cp.async.commit_group;\n" ::)
#define CPWAIT1 asm volatile("cp.async.wait_group 1;\n" ::)
#define CPWAIT0 asm volatile("cp.async.wait_group 0;\n" ::)

// ---------------- zero score accumulator -------------------------------------
__global__ __launch_bounds__(256) void zero_score_kernel() {
    g_score[blockIdx.x * 256 + threadIdx.x] = 0.f;
}

// ---------------- precision split of encoder_outputs and attn_W[:,H:] --------
__global__ __launch_bounds__(256) void conv_enc_kernel(const float *__restrict__ enc) {
    size_t idx = (size_t)blockIdx.x * 256 + threadIdx.x;  // float4 index
    float4 v4 = ((const float4 *)enc)[idx];
    __nv_bfloat16 h0, h1, h2, h3, l0, l1, l2, l3;
    splitf(v4.x, h0, l0); splitf(v4.y, h1, l1);
    splitf(v4.z, h2, l2); splitf(v4.w, h3, l3);
    ((__nv_bfloat162 *)g_enc_hi)[idx * 2 + 0] = __halves2bfloat162(h0, h1);
    ((__nv_bfloat162 *)g_enc_hi)[idx * 2 + 1] = __halves2bfloat162(h2, h3);
    ((__nv_bfloat162 *)g_enc_lo)[idx * 2 + 0] = __halves2bfloat162(l0, l1);
    ((__nv_bfloat162 *)g_enc_lo)[idx * 2 + 1] = __halves2bfloat162(l2, l3);
}

__global__ __launch_bounds__(256) void conv_w2_kernel(const float *__restrict__ attn_W) {
    size_t idx = (size_t)blockIdx.x * 256 + threadIdx.x;  // float4 index, 262144 total
    int n = (int)(idx >> 8);
    int k = (int)(idx & 255) << 2;
    float4 v4 = *(const float4 *)(attn_W + (size_t)n * 2048 + 1024 + k);
    __nv_bfloat16 h0, h1, h2, h3, l0, l1, l2, l3;
    splitf(v4.x, h0, l0); splitf(v4.y, h1, l1);
    splitf(v4.z, h2, l2); splitf(v4.w, h3, l3);
    size_t o = ((size_t)n * CH + k) >> 1;
    ((__nv_bfloat162 *)g_w2_hi)[o + 0] = __halves2bfloat162(h0, h1);
    ((__nv_bfloat162 *)g_w2_hi)[o + 1] = __halves2bfloat162(h2, h3);
    ((__nv_bfloat162 *)g_w2_lo)[o + 0] = __halves2bfloat162(l0, l1);
    ((__nv_bfloat162 *)g_w2_lo)[o + 1] = __halves2bfloat162(l2, l3);
}

// ---------------- dedicated small GEMM: hW = hidden @ W1^T + attn_b ----------
// grid 64 (n-chunks of 16), block 256. Tile: all 128 b x 16 n, K chunks of 64.
__global__ __launch_bounds__(256) void hw_kernel(const float *__restrict__ hidden,
                                                 const float *__restrict__ attn_W,
                                                 const float *__restrict__ attn_b) {
    __shared__ float Hs[128][65];
    __shared__ float Ws[16][65];
    const int tid = threadIdx.x;
    const int n0 = blockIdx.x * 16;
    const int bt = tid & 63;   // b pair index
    const int nt = tid >> 6;   // n quad index (constant per warp)
    float acc[2][4] = {{0.f, 0.f, 0.f, 0.f}, {0.f, 0.f, 0.f, 0.f}};

    for (int kc = 0; kc < 16; ++kc) {
        const int k0 = kc * 64;
#pragma unroll
        for (int i = 0; i < 8; ++i) {
            int idx = tid + 256 * i;
            int row = idx >> 4;
            int cv = (idx & 15) << 2;
            float4 v4 = *(const float4 *)(hidden + (size_t)row * CH + k0 + cv);
            Hs[row][cv] = v4.x; Hs[row][cv + 1] = v4.y;
            Hs[row][cv + 2] = v4.z; Hs[row][cv + 3] = v4.w;
        }
        {
            int row = tid >> 4;
            int cv = (tid & 15) << 2;
            float4 v4 = *(const float4 *)(attn_W + (size_t)(n0 + row) * 2048 + k0 + cv);
            Ws[row][cv] = v4.x; Ws[row][cv + 1] = v4.y;
            Ws[row][cv + 2] = v4.z; Ws[row][cv + 3] = v4.w;
        }
        __syncthreads();
#pragma unroll 8
        for (int k = 0; k < 64; ++k) {
            float w0 = Ws[nt * 4 + 0][k], w1 = Ws[nt * 4 + 1][k];
            float w2 = Ws[nt * 4 + 2][k], w3 = Ws[nt * 4 + 3][k];
            float h0 = Hs[bt * 2 + 0][k], h1 = Hs[bt * 2 + 1][k];
            acc[0][0] += h0 * w0; acc[0][1] += h0 * w1;
            acc[0][2] += h0 * w2; acc[0][3] += h0 * w3;
            acc[1][0] += h1 * w0; acc[1][1] += h1 * w1;
            acc[1][2] += h1 * w2; acc[1][3] += h1 * w3;
        }
        __syncthreads();
    }
#pragma unroll
    for (int i = 0; i < 2; ++i)
#pragma unroll
        for (int j = 0; j < 4; ++j) {
            int n = n0 + nt * 4 + j;
            g_hW[(size_t)(bt * 2 + i) * CH + n] = acc[i][j] + attn_b[n];
        }
}

// ---------------- generic bf16-split x3 GEMM: C[M,N] = A@B^T (+bias) ---------
__global__ __launch_bounds__(256) void gemm_kernel(
    const float *__restrict__ A, const __nv_bfloat16 *__restrict__ Ahi,
    const __nv_bfloat16 *__restrict__ Alo, int lda,
    const float *__restrict__ B1, int ldb1, int ksw,
    const float *__restrict__ B2, int ldb2,
    const float *__restrict__ bias1, const float *__restrict__ bias2,
    float *__restrict__ C, int ldc, int K) {
    __shared__ __align__(16) __nv_bfloat16 As_hi[128][40];
    __shared__ __align__(16) __nv_bfloat16 As_lo[128][40];
    __shared__ __align__(16) __nv_bfloat16 Bs_hi[64][40];
    __shared__ __align__(16) __nv_bfloat16 Bs_lo[64][40];

    const int tid = threadIdx.x;
    const int lane = tid & 31;
    const int gid = lane >> 2;
    const int t4 = lane & 3;
    const int wm = (tid >> 5) >> 1;  // 0..3
    const int wn = (tid >> 5) & 1;   // 0..1
    const int m0 = blockIdx.y * 128;
    const int n0 = blockIdx.x * 64;

    // ldmatrix address offsets
    const int a_mrow = (lane & 15);
    const int a_koff = (lane >> 4) << 3;
    const int b_nrow = (lane & 7) + ((lane >> 4) << 3);
    const int b_koff = ((lane >> 3) & 1) << 3;

    float acc[2][4][4];
#pragma unroll
    for (int i = 0; i < 2; i++)
#pragma unroll
        for (int j = 0; j < 4; j++)
#pragma unroll
            for (int c = 0; c < 4; c++) acc[i][j][c] = 0.f;

    for (int k0 = 0; k0 < K; k0 += 32) {
        if (Ahi) {
#pragma unroll
            for (int i = 0; i < 2; ++i) {
                int idx = tid + i * 256;  // uint4 over 512
                int row = idx >> 2;
                int col = (idx & 3) << 3;
                *(uint4 *)&As_hi[row][col] =
                    *(const uint4 *)(Ahi + (size_t)(m0 + row) * lda + k0 + col);
                *(uint4 *)&As_lo[row][col] =
                    *(const uint4 *)(Alo + (size_t)(m0 + row) * lda + k0 + col);
            }
        } else {
#pragma unroll
            for (int i = 0; i < 4; ++i) {
                int idx = tid + i * 256;  // float4 over 1024
                int row = idx >> 3;
                int col = (idx & 7) << 2;
                float4 v4 = *(const float4 *)(A + (size_t)(m0 + row) * lda + k0 + col);
                __nv_bfloat16 h0, h1, h2, h3, l0, l1, l2, l3;
                splitf(v4.x, h0, l0); splitf(v4.y, h1, l1);
                splitf(v4.z, h2, l2); splitf(v4.w, h3, l3);
                *(__nv_bfloat162 *)&As_hi[row][col]     = __halves2bfloat162(h0, h1);
                *(__nv_bfloat162 *)&As_hi[row][col + 2] = __halves2bfloat162(h2, h3);
                *(__nv_bfloat162 *)&As_lo[row][col]     = __halves2bfloat162(l0, l1);
                *(__nv_bfloat162 *)&As_lo[row][col + 2] = __halves2bfloat162(l2, l3);
            }
        }
#pragma unroll
        for (int i = 0; i < 2; ++i) {
            int idx = tid + i * 256;  // float4 over 512
            int row = idx >> 3;
            int col = (idx & 7) << 2;
            int n = n0 + row;
            int k = k0 + col;
            const float *src = (k < ksw) ? (B1 + (size_t)n * ldb1 + k)
                                         : (B2 + (size_t)n * ldb2 + (k - ksw));
            float4 v4 = *(const float4 *)src;
            __nv_bfloat16 h0, h1, h2, h3, l0, l1, l2, l3;
            splitf(v4.x, h0, l0); splitf(v4.y, h1, l1);
            splitf(v4.z, h2, l2); splitf(v4.w, h3, l3);
            *(__nv_bfloat162 *)&Bs_hi[row][col]     = __halves2bfloat162(h0, h1);
            *(__nv_bfloat162 *)&Bs_hi[row][col + 2] = __halves2bfloat162(h2, h3);
            *(__nv_bfloat162 *)&Bs_lo[row][col]     = __halves2bfloat162(l0, l1);
            *(__nv_bfloat162 *)&Bs_lo[row][col + 2] = __halves2bfloat162(l2, l3);
        }
        __syncthreads();
#pragma unroll
        for (int kk = 0; kk < 32; kk += 16) {
            uint32_t ah[2][4], al[2][4];
#pragma unroll
            for (int fm = 0; fm < 2; ++fm) {
                uint32_t ad = s2u(&As_hi[wm * 32 + fm * 16 + a_mrow][kk + a_koff]);
                ldsm4(ah[fm][0], ah[fm][1], ah[fm][2], ah[fm][3], ad);
                uint32_t ad2 = s2u(&As_lo[wm * 32 + fm * 16 + a_mrow][kk + a_koff]);
                ldsm4(al[fm][0], al[fm][1], al[fm][2], al[fm][3], ad2);
            }
#pragma unroll
            for (int fnp = 0; fnp < 2; ++fnp) {
                uint32_t bh[4], bl[4];
                uint32_t bd = s2u(&Bs_hi[wn * 32 + fnp * 16 + b_nrow][kk + b_koff]);
                ldsm4(bh[0], bh[1], bh[2], bh[3], bd);
                uint32_t bd2 = s2u(&Bs_lo[wn * 32 + fnp * 16 + b_nrow][kk + b_koff]);
                ldsm4(bl[0], bl[1], bl[2], bl[3], bd2);
#pragma unroll
                for (int fm = 0; fm < 2; ++fm) {
                    float *d0 = acc[fm][fnp * 2];
                    float *d1 = acc[fm][fnp * 2 + 1];
                    MMA16816(d0, ah[fm][0], ah[fm][1], ah[fm][2], ah[fm][3], bh[0], bh[1]);
                    MMA16816(d0, ah[fm][0], ah[fm][1], ah[fm][2], ah[fm][3], bl[0], bl[1]);
                    MMA16816(d0, al[fm][0], al[fm][1], al[fm][2], al[fm][3], bh[0], bh[1]);
                    MMA16816(d1, ah[fm][0], ah[fm][1], ah[fm][2], ah[fm][3], bh[2], bh[3]);
                    MMA16816(d1, ah[fm][0], ah[fm][1], ah[fm][2], ah[fm][3], bl[2], bl[3]);
                    MMA16816(d1, al[fm][0], al[fm][1], al[fm][2], al[fm][3], bh[2], bh[3]);
                }
            }
        }
        __syncthreads();
    }
#pragma unroll
    for (int fm = 0; fm < 2; ++fm)
#pragma unroll
        for (int fn = 0; fn < 4; ++fn) {
            int row = m0 + wm * 32 + fm * 16 + gid;
            int col = n0 + wn * 32 + fn * 8 + (t4 << 1);
            float b0 = 0.f, b1 = 0.f;
            if (bias1) { b0 += bias1[col]; b1 += bias1[col + 1]; }
            if (bias2) { b0 += bias2[col]; b1 += bias2[col + 1]; }
            C[(size_t)row * ldc + col]           = acc[fm][fn][0] + b0;
            C[(size_t)row * ldc + col + 1]       = acc[fm][fn][1] + b1;
            C[(size_t)(row + 8) * ldc + col]     = acc[fm][fn][2] + b0;
            C[(size_t)(row + 8) * ldc + col + 1] = acc[fm][fn][3] + b1;
        }
}

// ---------------- fused energy GEMM + tanh + v-dot -> score[B,S] -------------
// Grid (8, 128): blockIdx.y = batch b, blockIdx.x = n-chunk (128 cols of H).
// CTA: GEMM 128x128x1024 (bf16 split x3), epilogue tanh+v-dot, atomicAdd into
// g_score[b,:]. cp.async 2-stage double buffered; warps 4x2, warp tile 32x64.
#define AS_STRIDE 40
#define AS_STAGE (128 * AS_STRIDE)
#define ATTN_SMEM_BYTES ((4 * 2 * AS_STAGE) * 2 + 128 * 4)

__global__ __launch_bounds__(256, 2) void attn_score_kernel(const float *__restrict__ v) {
    extern __shared__ __align__(16) __nv_bfloat16 smem[];
    __nv_bfloat16 *AsHi = smem;
    __nv_bfloat16 *AsLo = AsHi + 2 * AS_STAGE;
    __nv_bfloat16 *BsHi = AsLo + 2 * AS_STAGE;
    __nv_bfloat16 *BsLo = BsHi + 2 * AS_STAGE;
    float *red = (float *)(BsLo + 2 * AS_STAGE);

    const int b = blockIdx.y;
    const int n0 = blockIdx.x * 128;
    const int tid = threadIdx.x;
    const int lane = tid & 31;
    const int gid = lane >> 2;
    const int t4 = lane & 3;
    const int wm = (tid >> 5) >> 1;  // 0..3 (m tile of 32)
    const int wn = (tid >> 5) & 1;   // 0..1 (n tile of 64)
    if (tid < 128) red[tid] = 0.f;

    const int a_mrow = (lane & 15);
    const int a_koff = (lane >> 4) << 3;
    const int b_nrow = (lane & 7) + ((lane >> 4) << 3);
    const int b_koff = ((lane >> 3) & 1) << 3;

    // stage loader indices (16B chunks)
    const int ld_row = tid >> 2;
    const int ld_col = (tid & 3) << 3;

    float acc[2][8][4];
#pragma unroll
    for (int i = 0; i < 2; i++)
#pragma unroll
        for (int j = 0; j < 8; j++)
#pragma unroll
            for (int c = 0; c < 4; c++) acc[i][j][c] = 0.f;

#define LOAD_STAGE(st, k0)                                                     \
    do {                                                                       \
        _Pragma("unroll") for (int i = 0; i < 2; ++i) {                        \
            int row = ld_row + i * 64;                                         \
            size_t goA = (size_t)(b * 128 + row) * CH + (k0) + ld_col;         \
            size_t goB = (size_t)(n0 + row) * CH + (k0) + ld_col;              \
            uint32_t dof = (st) * AS_STAGE + row * AS_STRIDE + ld_col;         \
            CPASYNC16(s2u(AsHi + dof), g_enc_hi + goA);                        \
            CPASYNC16(s2u(AsLo + dof), g_enc_lo + goA);                        \
            CPASYNC16(s2u(BsHi + dof), g_w2_hi + goB);                         \
            CPASYNC16(s2u(BsLo + dof), g_w2_lo + goB);                         \
        }                                                                      \
        CPCOMMIT;                                                              \
    } while (0)

    LOAD_STAGE(0, 0);
    for (int kt = 0; kt < 32; ++kt) {
        if (kt + 1 < 32) {
            LOAD_STAGE((kt + 1) & 1, (kt + 1) * 32);
            CPWAIT1;
        } else {
            CPWAIT0;
        }
        __syncthreads();
        const int cur = kt & 1;
        const __nv_bfloat16 *cAH = AsHi + cur * AS_STAGE;
        const __nv_bfloat16 *cAL = AsLo + cur * AS_STAGE;
        const __nv_bfloat16 *cBH = BsHi + cur * AS_STAGE;
        const __nv_bfloat16 *cBL = BsLo + cur * AS_STAGE;
#pragma unroll
        for (int kk = 0; kk < 32; kk += 16) {
            uint32_t ah[2][4], al[2][4];
#pragma unroll
            for (int fm = 0; fm < 2; ++fm) {
                int rowb = wm * 32 + fm * 16 + a_mrow;
                ldsm4(ah[fm][0], ah[fm][1], ah[fm][2], ah[fm][3],
                      s2u(cAH + rowb * AS_STRIDE + kk + a_koff));
                ldsm4(al[fm][0], al[fm][1], al[fm][2], al[fm][3],
                      s2u(cAL + rowb * AS_STRIDE + kk + a_koff));
            }
#pragma unroll
            for (int fnp = 0; fnp < 4; ++fnp) {
                uint32_t bh[4], bl[4];
                int nrow = wn * 64 + fnp * 16 + b_nrow;
                ldsm4(bh[0], bh[1], bh[2], bh[3],
                      s2u(cBH + nrow * AS_STRIDE + kk + b_koff));
                ldsm4(bl[0], bl[1], bl[2], bl[3],
                      s2u(cBL + nrow * AS_STRIDE + kk + b_koff));
#pragma unroll
                for (int fm = 0; fm < 2; ++fm) {
                    float *d0 = acc[fm][fnp * 2];
                    float *d1 = acc[fm][fnp * 2 + 1];
                    MMA16816(d0, ah[fm][0], ah[fm][1], ah[fm][2], ah[fm][3], bh[0], bh[1]);
                    MMA16816(d0, ah[fm][0], ah[fm][1], ah[fm][2], ah[fm][3], bl[0], bl[1]);
                    MMA16816(d0, al[fm][0], al[fm][1], al[fm][2], al[fm][3], bh[0], bh[1]);
                    MMA16816(d1, ah[fm][0], ah[fm][1], ah[fm][2], ah[fm][3], bh[2], bh[3]);
                    MMA16816(d1, ah[fm][0], ah[fm][1], ah[fm][2], ah[fm][3], bl[2], bl[3]);
                    MMA16816(d1, al[fm][0], al[fm][1], al[fm][2], al[fm][3], bh[2], bh[3]);
                }
            }
        }
        __syncthreads();
    }

    // epilogue: tanh(energy + hW) * v, partial per-row sums
    const float *hWb = g_hW + (size_t)b * CH;
    float pA[2] = {0.f, 0.f}, pB[2] = {0.f, 0.f};
#pragma unroll
    for (int fm = 0; fm < 2; ++fm)
#pragma unroll
        for (int fn = 0; fn < 8; ++fn) {
            int col = n0 + wn * 64 + fn * 8 + (t4 << 1);
            float hw0 = hWb[col], hw1 = hWb[col + 1];
            float v0 = v[col], v1 = v[col + 1];
            pA[fm] += tanhf(acc[fm][fn][0] + hw0) * v0 +
                      tanhf(acc[fm][fn][1] + hw1) * v1;
            pB[fm] += tanhf(acc[fm][fn][2] + hw0) * v0 +
                      tanhf(acc[fm][fn][3] + hw1) * v1;
        }
#pragma unroll
    for (int fm = 0; fm < 2; ++fm)
#pragma unroll
        for (int j = 0; j < 2; ++j) {
            float val = j ? pB[fm] : pA[fm];
            val += __shfl_xor_sync(0xffffffffu, val, 1);
            val += __shfl_xor_sync(0xffffffffu, val, 2);
            if (t4 == 0) atomicAdd(&red[wm * 32 + fm * 16 + j * 8 + gid], val);
        }
    __syncthreads();
    if (tid < 128) atomicAdd(&g_score[b * 128 + tid], red[tid]);
}

// ---------------- softmax over S, writes attn output + weights in place ------
__global__ __launch_bounds__(128) void softmax_kernel(float *__restrict__ out_attn) {
    const int b = blockIdx.x;
    const int t = threadIdx.x;
    __shared__ float sm[128];
    float s = g_score[b * 128 + t];
    sm[t] = s;
    __syncthreads();
#pragma unroll
    for (int st = 64; st > 0; st >>= 1) {
        if (t < st) sm[t] = fmaxf(sm[t], sm[t + st]);
        __syncthreads();
    }
    float mx = sm[0];
    __syncthreads();
    float e = expf(s - mx);
    sm[t] = e;
    __syncthreads();
#pragma unroll
    for (int st = 64; st > 0; st >>= 1) {
        if (t < st) sm[t] += sm[t + st];
        __syncthreads();
    }
    float w = e / sm[0];
    g_score[b * 128 + t] = w;
    out_attn[b * 128 + t] = w;
}

// ---------------- context + assemble xin (emb|context|h_last) ----------------
__global__ __launch_bounds__(256) void context_kernel(
    const int *__restrict__ x, const float *__restrict__ emb_table,
    const float *__restrict__ hidden, const float *__restrict__ enc) {
    const int b = blockIdx.x;
    const int t = threadIdx.x;
    __shared__ float w_s[128];
    if (t < 128) w_s[t] = g_score[b * 128 + t];
    int tok = x[b];
    for (int i = t; i < CE; i += 256)
        g_xin[(size_t)b * 2560 + i] = emb_table[(size_t)tok * CE + i];
    for (int i = t; i < CH; i += 256)
        g_xin[(size_t)b * 2560 + 1536 + i] = hidden[(size_t)b * CH + i];
    __syncthreads();
    float acc[4] = {0.f, 0.f, 0.f, 0.f};
    const float *encb = enc + (size_t)b * CS * CH;
    for (int s = 0; s < CS; ++s) {
        float w = w_s[s];
        const float *er = encb + (size_t)s * CH;
#pragma unroll
        for (int i = 0; i < 4; ++i) acc[i] += w * er[t + i * 256];
    }
#pragma unroll
    for (int i = 0; i < 4; ++i) {
        int h = t + i * 256;
        float c = acc[i];
        g_xin[(size_t)b * 2560 + 512 + h] = c;
        __nv_bfloat16 hi, lo;
        splitf(c, hi, lo);
        g_out2_hi[(size_t)b * 2048 + 1024 + h] = hi;
        g_out2_lo[(size_t)b * 2048 + 1024 + h] = lo;
    }
}

// ---------------- LSTM pointwise ---------------------------------------------
__global__ __launch_bounds__(256) void lstm_kernel(
    const float *__restrict__ cell, float *__restrict__ out_h,
    float *__restrict__ out_c) {
    int id = blockIdx.x * 256 + threadIdx.x;  // 131072
    int b = id >> 10;
    int h = id & 1023;
    const float *gt = g_gates + (size_t)b * 4096;
    float gi = gt[h], gf = gt[1024 + h], gg = gt[2048 + h], go = gt[3072 + h];
    float c_old = cell[(size_t)b * CH + h];
    float cn = sigf(gf) * c_old + sigf(gi) * tanhf(gg);
    float hn = sigf(go) * tanhf(cn);
    out_h[(size_t)b * CH + h] = hn;
    out_c[(size_t)b * CH + h] = cn;
    __nv_bfloat16 hi, lo;
    splitf(hn, hi, lo);
    g_out2_hi[(size_t)b * 2048 + h] = hi;
    g_out2_lo[(size_t)b * 2048 + h] = lo;
}

// ---------------- launch ------------------------------------------------------
extern "C" void kernel_launch(void *const *d_in, const int *in_sizes, int n_in,
                              void *d_out, int out_size) {
    (void)in_sizes; (void)n_in; (void)out_size;
    const int *x           = (const int *)d_in[0];
    const float *hidden    = (const float *)d_in[1];
    const float *cell      = (const float *)d_in[2];
    const float *enc       = (const float *)d_in[3];
    const float *emb_table = (const float *)d_in[4];
    const float *attn_W    = (const float *)d_in[5];
    const float *attn_b    = (const float *)d_in[6];
    const float *v         = (const float *)d_in[7];
    const float *W_ih      = (const float *)d_in[8];
    const float *W_hh      = (const float *)d_in[9];
    const float *b_ih      = (const float *)d_in[10];
    const float *b_hh      = (const float *)d_in[11];
    const float *fc_W      = (const float *)d_in[12];
    const float *fc_b      = (const float *)d_in[13];

    float *out        = (float *)d_out;
    float *out_logits = out;
    float *out_h      = out + (size_t)CB * CV;
    float *out_c      = out_h + (size_t)CB * CH;
    float *out_attn   = out_c + (size_t)CB * CH;

    float *xinp = nullptr, *gatesp = nullptr;
    __nv_bfloat16 *o2h = nullptr, *o2l = nullptr;
    cudaGetSymbolAddress((void **)&xinp, g_xin);
    cudaGetSymbolAddress((void **)&gatesp, g_gates);
    cudaGetSymbolAddress((void **)&o2h, g_out2_hi);
    cudaGetSymbolAddress((void **)&o2l, g_out2_lo);

    cudaFuncSetAttribute(attn_score_kernel,
                         cudaFuncAttributeMaxDynamicSharedMemorySize,
                         ATTN_SMEM_BYTES);

    // 0) zero the score accumulator
    zero_score_kernel<<<64, 256>>>();

    // 1) precision-split encoder_outputs and attn_W[:, H:2H]
    conv_enc_kernel<<<16384, 256>>>(enc);
    conv_w2_kernel<<<1024, 256>>>(attn_W);

    // 2) hW = h_last @ attn_W[:, :H]^T + attn_b   -> g_hW [B,H]
    hw_kernel<<<64, 256>>>(hidden, attn_W, attn_b);

    // 3) fused energy GEMM + tanh + v-dot -> g_score [B,S]  (8 n-chunks x 128 b)
    attn_score_kernel<<<dim3(8, CB), 256, ATTN_SMEM_BYTES>>>(v);

    // 4) softmax -> attn_weights (output) + g_score in place
    softmax_kernel<<<CB, 128>>>(out_attn);

    // 5) context = w @ enc ; assemble xin = [emb|context|h_last], out2 ctx half
    context_kernel<<<CB, 256>>>(x, emb_table, hidden, enc);

    // 6) gates = xin @ [W_ih|W_hh]^T + b_ih + b_hh   (K = 1536 + 1024)
    gemm_kernel<<<dim3(4096 / 64, 1), 256>>>(
        xinp, nullptr, nullptr, 2560,
        W_ih, 1536, 1536, W_hh, CH,
        b_ih, b_hh, gatesp, 4096, 2560);

    // 7) LSTM pointwise -> h_new, c_new outputs + out2 h half (bf16 split)
    lstm_kernel<<<(CB * CH) / 256, 256>>>(cell, out_h, out_c);

    // 8) logits = [h_new|context] @ fc_W^T + fc_b
    gemm_kernel<<<dim3(CV / 64, 1), 256>>>(
        nullptr, o2h, o2l, 2048,
        fc_W, 2048, 2048, nullptr, 0,
        fc_b, nullptr, out_logits, CV, 2048);
}

// round 5
// speedup vs baseline: 1.8486x; 1.3731x over previous
#include <cuda_runtime.h>
#include <cuda_bf16.h>
#include <stdint.h>
#include <math.h>

#define CB 128
#define CS 128
#define CH 1024
#define CE 512
#define CV 32000

// ---------------- scratch (__device__ globals; no allocations allowed) -------
__device__ __align__(16) float g_hW[CB * CH];
__device__ __align__(16) float g_score[CB * CS];
__device__ __align__(16) float g_gates[CB * 4096];
__device__ __align__(16) __nv_bfloat16 g_xin_hi[CB * 2560];   // [emb|context|h_last]
__device__ __align__(16) __nv_bfloat16 g_xin_lo[CB * 2560];
__device__ __align__(16) __nv_bfloat16 g_out2_hi[CB * 2048];  // [h_new | context]
__device__ __align__(16) __nv_bfloat16 g_out2_lo[CB * 2048];
__device__ __align__(16) __nv_bfloat16 g_enc_hi[CB * CS * CH];
__device__ __align__(16) __nv_bfloat16 g_enc_lo[CB * CS * CH];
__device__ __align__(16) __nv_bfloat16 g_w2_hi[CH * CH];      // attn_W[:, H:2H] as [n][k]
__device__ __align__(16) __nv_bfloat16 g_w2_lo[CH * CH];

// ---------------- helpers ----------------------------------------------------
__device__ __forceinline__ void splitf(float x, __nv_bfloat16 &hi, __nv_bfloat16 &lo) {
    hi = __float2bfloat16_rn(x);
    lo = __float2bfloat16_rn(x - __bfloat162float(hi));
}
__device__ __forceinline__ float sigf(float x) { return 1.0f / (1.0f + expf(-x)); }
__device__ __forceinline__ uint32_t s2u(const void *p) {
    return (uint32_t)__cvta_generic_to_shared(p);
}
__device__ __forceinline__ void ldsm4(uint32_t &r0, uint32_t &r1, uint32_t &r2,
                                      uint32_t &r3, uint32_t addr) {
    asm volatile("ldmatrix.sync.aligned.m8n8.x4.shared.b16 {%0,%1,%2,%3}, [%4];"
                 : "=r"(r0), "=r"(r1), "=r"(r2), "=r"(r3)
                 : "r"(addr));
}

#define MMA16816(d, a0, a1, a2, a3, b0, b1)                                    \
    asm volatile(                                                              \
        "mma.sync.aligned.m16n8k16.row.col.f32.bf16.bf16.f32 "                 \
        "{%0,%1,%2,%3},{%4,%5,%6,%7},{%8,%9},{%0,%1,%2,%3};\n"                 \
        : "+f"(d[0]), "+f"(d[1]), "+f"(d[2]), "+f"(d[3])                       \
        : "r"(a0), "r"(a1), "r"(a2), "r"(a3), "r"(b0), "r"(b1))

#define CPASYNC16(dst, src)                                                    \
    asm volatile("cp.async.cg.shared.global [%0], [%1], 16;\n" ::"r"(dst),     \
                 "l"(src))
#define CPCOMMIT asm volatile("cp.async.commit_group;\n" ::)
#define CPWAIT1 asm volatile("cp.async.wait_group 1;\n" ::)
#define CPWAIT0 asm volatile("cp.async.wait_group 0;\n" ::)

// ---------------- precision split of encoder_outputs and attn_W[:,H:] --------
__global__ __launch_bounds__(256) void conv_enc_kernel(const float *__restrict__ enc) {
    size_t idx = (size_t)blockIdx.x * 256 + threadIdx.x;  // float4 index
    float4 v4 = ((const float4 *)enc)[idx];
    __nv_bfloat16 h0, h1, h2, h3, l0, l1, l2, l3;
    splitf(v4.x, h0, l0); splitf(v4.y, h1, l1);
    splitf(v4.z, h2, l2); splitf(v4.w, h3, l3);
    ((__nv_bfloat162 *)g_enc_hi)[idx * 2 + 0] = __halves2bfloat162(h0, h1);
    ((__nv_bfloat162 *)g_enc_hi)[idx * 2 + 1] = __halves2bfloat162(h2, h3);
    ((__nv_bfloat162 *)g_enc_lo)[idx * 2 + 0] = __halves2bfloat162(l0, l1);
    ((__nv_bfloat162 *)g_enc_lo)[idx * 2 + 1] = __halves2bfloat162(l2, l3);
}

// also zeroes g_score and seeds g_hW with attn_b (pre-atomic accumulator init)
__global__ __launch_bounds__(256) void conv_w2_kernel(const float *__restrict__ attn_W,
                                                      const float *__restrict__ attn_b) {
    size_t idx = (size_t)blockIdx.x * 256 + threadIdx.x;  // float4 index, 262144 total
    if (blockIdx.x < 64) g_score[blockIdx.x * 256 + threadIdx.x] = 0.f;
    if (blockIdx.x < 512) {
        int i = blockIdx.x * 256 + threadIdx.x;  // 131072 floats of g_hW
        g_hW[i] = attn_b[i & (CH - 1)];
    }
    int n = (int)(idx >> 8);
    int k = (int)(idx & 255) << 2;
    float4 v4 = *(const float4 *)(attn_W + (size_t)n * 2048 + 1024 + k);
    __nv_bfloat16 h0, h1, h2, h3, l0, l1, l2, l3;
    splitf(v4.x, h0, l0); splitf(v4.y, h1, l1);
    splitf(v4.z, h2, l2); splitf(v4.w, h3, l3);
    size_t o = ((size_t)n * CH + k) >> 1;
    ((__nv_bfloat162 *)g_w2_hi)[o + 0] = __halves2bfloat162(h0, h1);
    ((__nv_bfloat162 *)g_w2_hi)[o + 1] = __halves2bfloat162(h2, h3);
    ((__nv_bfloat162 *)g_w2_lo)[o + 0] = __halves2bfloat162(l0, l1);
    ((__nv_bfloat162 *)g_w2_lo)[o + 1] = __halves2bfloat162(l2, l3);
}

// ---------------- small GEMM: hW += hidden @ W1^T (K-split, atomic) ----------
// grid (64, 4): x = n-chunk of 16, y = K-chunk of 256. g_hW pre-seeded w/ bias.
__global__ __launch_bounds__(256) void hw_kernel(const float *__restrict__ hidden,
                                                 const float *__restrict__ attn_W) {
    __shared__ float Hs[128][65];
    __shared__ float Ws[16][65];
    const int tid = threadIdx.x;
    const int n0 = blockIdx.x * 16;
    const int kbase = blockIdx.y * 256;
    const int bt = tid & 63;   // b pair index
    const int nt = tid >> 6;   // n quad index
    float acc[2][4] = {{0.f, 0.f, 0.f, 0.f}, {0.f, 0.f, 0.f, 0.f}};

    for (int kc = 0; kc < 4; ++kc) {
        const int k0 = kbase + kc * 64;
#pragma unroll
        for (int i = 0; i < 8; ++i) {
            int idx = tid + 256 * i;
            int row = idx >> 4;
            int cv = (idx & 15) << 2;
            float4 v4 = *(const float4 *)(hidden + (size_t)row * CH + k0 + cv);
            Hs[row][cv] = v4.x; Hs[row][cv + 1] = v4.y;
            Hs[row][cv + 2] = v4.z; Hs[row][cv + 3] = v4.w;
        }
        {
            int row = tid >> 4;
            int cv = (tid & 15) << 2;
            float4 v4 = *(const float4 *)(attn_W + (size_t)(n0 + row) * 2048 + k0 + cv);
            Ws[row][cv] = v4.x; Ws[row][cv + 1] = v4.y;
            Ws[row][cv + 2] = v4.z; Ws[row][cv + 3] = v4.w;
        }
        __syncthreads();
#pragma unroll 8
        for (int k = 0; k < 64; ++k) {
            float w0 = Ws[nt * 4 + 0][k], w1 = Ws[nt * 4 + 1][k];
            float w2 = Ws[nt * 4 + 2][k], w3 = Ws[nt * 4 + 3][k];
            float h0 = Hs[bt * 2 + 0][k], h1 = Hs[bt * 2 + 1][k];
            acc[0][0] += h0 * w0; acc[0][1] += h0 * w1;
            acc[0][2] += h0 * w2; acc[0][3] += h0 * w3;
            acc[1][0] += h1 * w0; acc[1][1] += h1 * w1;
            acc[1][2] += h1 * w2; acc[1][3] += h1 * w3;
        }
        __syncthreads();
    }
#pragma unroll
    for (int i = 0; i < 2; ++i)
#pragma unroll
        for (int j = 0; j < 4; ++j) {
            int n = n0 + nt * 4 + j;
            atomicAdd(&g_hW[(size_t)(bt * 2 + i) * CH + n], acc[i][j]);
        }
}

// ---------------- pipelined bf16-split x3 GEMM: C = A@B^T (+bias) ------------
// A: pre-split bf16 hi/lo [M=128, lda], loaded via cp.async (2 stages).
// B: fp32, register-staged one k-tile ahead, split to bf16 in-kernel.
// Tile 128 x 64 x 32. grid.x = N/64.
#define A2_STAGE (128 * 40)
#define B2_STAGE (64 * 40)
#define G2_SMEM_BYTES ((2 * A2_STAGE * 2 + 2 * B2_STAGE * 2) * 2)

__global__ __launch_bounds__(256, 2) void gemm2_kernel(
    const __nv_bfloat16 *__restrict__ Ahi, const __nv_bfloat16 *__restrict__ Alo,
    int lda,
    const float *__restrict__ B1, int ldb1, int ksw,
    const float *__restrict__ B2, int ldb2,
    const float *__restrict__ bias1, const float *__restrict__ bias2,
    float *__restrict__ C, int ldc, int K) {
    extern __shared__ __align__(16) __nv_bfloat16 sm2[];
    __nv_bfloat16 *AsHi = sm2;
    __nv_bfloat16 *AsLo = AsHi + 2 * A2_STAGE;
    __nv_bfloat16 *BsHi = AsLo + 2 * A2_STAGE;
    __nv_bfloat16 *BsLo = BsHi + 2 * B2_STAGE;

    const int tid = threadIdx.x;
    const int lane = tid & 31;
    const int gid = lane >> 2;
    const int t4 = lane & 3;
    const int wm = (tid >> 5) >> 1;  // 0..3
    const int wn = (tid >> 5) & 1;   // 0..1
    const int n0 = blockIdx.x * 64;

    const int a_mrow = (lane & 15);
    const int a_koff = (lane >> 4) << 3;
    const int b_nrow = (lane & 7) + ((lane >> 4) << 3);
    const int b_koff = ((lane >> 3) & 1) << 3;

    const int nk = K >> 5;

    float acc[2][4][4];
#pragma unroll
    for (int i = 0; i < 2; i++)
#pragma unroll
        for (int j = 0; j < 4; j++)
#pragma unroll
            for (int c = 0; c < 4; c++) acc[i][j][c] = 0.f;

    float4 breg[2];
    auto ldB = [&](int k0) {
#pragma unroll
        for (int i = 0; i < 2; ++i) {
            int idx = tid + i * 256;
            int row = n0 + (idx >> 3);
            int k = k0 + ((idx & 7) << 2);
            const float *src = (k < ksw) ? (B1 + (size_t)row * ldb1 + k)
                                         : (B2 + (size_t)row * ldb2 + (k - ksw));
            breg[i] = *(const float4 *)src;
        }
    };
    auto stB = [&](int st) {
#pragma unroll
        for (int i = 0; i < 2; ++i) {
            int idx = tid + i * 256;
            int row = idx >> 3;
            int col = (idx & 7) << 2;
            __nv_bfloat16 h0, h1, h2, h3, l0, l1, l2, l3;
            splitf(breg[i].x, h0, l0); splitf(breg[i].y, h1, l1);
            splitf(breg[i].z, h2, l2); splitf(breg[i].w, h3, l3);
            __nv_bfloat16 *dh = BsHi + st * B2_STAGE + row * 40 + col;
            __nv_bfloat16 *dl = BsLo + st * B2_STAGE + row * 40 + col;
            *(__nv_bfloat162 *)dh       = __halves2bfloat162(h0, h1);
            *(__nv_bfloat162 *)(dh + 2) = __halves2bfloat162(h2, h3);
            *(__nv_bfloat162 *)dl       = __halves2bfloat162(l0, l1);
            *(__nv_bfloat162 *)(dl + 2) = __halves2bfloat162(l2, l3);
        }
    };
    auto cpA = [&](int st, int k0) {
#pragma unroll
        for (int i = 0; i < 2; ++i) {
            int idx = tid + i * 256;  // 512 chunks of 16B (128 rows x 4)
            int row = idx >> 2;
            int col = (idx & 3) << 3;
            uint32_t dof = st * A2_STAGE + row * 40 + col;
            size_t go = (size_t)row * lda + k0 + col;
            CPASYNC16(s2u(AsHi + dof), Ahi + go);
            CPASYNC16(s2u(AsLo + dof), Alo + go);
        }
        CPCOMMIT;
    };

    cpA(0, 0);
    ldB(0);
    for (int kt = 0; kt < nk; ++kt) {
        const int st = kt & 1;
        stB(st);
        if (kt + 1 < nk) {
            cpA((kt + 1) & 1, (kt + 1) * 32);
            CPWAIT1;
        } else {
            CPWAIT0;
        }
        __syncthreads();
        if (kt + 1 < nk) ldB((kt + 1) * 32);
        const __nv_bfloat16 *cAH = AsHi + st * A2_STAGE;
        const __nv_bfloat16 *cAL = AsLo + st * A2_STAGE;
        const __nv_bfloat16 *cBH = BsHi + st * B2_STAGE;
        const __nv_bfloat16 *cBL = BsLo + st * B2_STAGE;
#pragma unroll
        for (int kk = 0; kk < 32; kk += 16) {
            uint32_t ah[2][4], al[2][4];
#pragma unroll
            for (int fm = 0; fm < 2; ++fm) {
                int rowb = wm * 32 + fm * 16 + a_mrow;
                ldsm4(ah[fm][0], ah[fm][1], ah[fm][2], ah[fm][3],
                      s2u(cAH + rowb * 40 + kk + a_koff));
                ldsm4(al[fm][0], al[fm][1], al[fm][2], al[fm][3],
                      s2u(cAL + rowb * 40 + kk + a_koff));
            }
#pragma unroll
            for (int fnp = 0; fnp < 2; ++fnp) {
                uint32_t bh[4], bl[4];
                int nrow = wn * 32 + fnp * 16 + b_nrow;
                ldsm4(bh[0], bh[1], bh[2], bh[3],
                      s2u(cBH + nrow * 40 + kk + b_koff));
                ldsm4(bl[0], bl[1], bl[2], bl[3],
                      s2u(cBL + nrow * 40 + kk + b_koff));
#pragma unroll
                for (int fm = 0; fm < 2; ++fm) {
                    float *d0 = acc[fm][fnp * 2];
                    float *d1 = acc[fm][fnp * 2 + 1];
                    MMA16816(d0, ah[fm][0], ah[fm][1], ah[fm][2], ah[fm][3], bh[0], bh[1]);
                    MMA16816(d0, ah[fm][0], ah[fm][1], ah[fm][2], ah[fm][3], bl[0], bl[1]);
                    MMA16816(d0, al[fm][0], al[fm][1], al[fm][2], al[fm][3], bh[0], bh[1]);
                    MMA16816(d1, ah[fm][0], ah[fm][1], ah[fm][2], ah[fm][3], bh[2], bh[3]);
                    MMA16816(d1, ah[fm][0], ah[fm][1], ah[fm][2], ah[fm][3], bl[2], bl[3]);
                    MMA16816(d1, al[fm][0], al[fm][1], al[fm][2], al[fm][3], bh[2], bh[3]);
                }
            }
        }
        __syncthreads();
    }
#pragma unroll
    for (int fm = 0; fm < 2; ++fm)
#pragma unroll
        for (int fn = 0; fn < 4; ++fn) {
            int row = wm * 32 + fm * 16 + gid;
            int col = n0 + wn * 32 + fn * 8 + (t4 << 1);
            float b0 = 0.f, b1 = 0.f;
            if (bias1) { b0 += bias1[col]; b1 += bias1[col + 1]; }
            if (bias2) { b0 += bias2[col]; b1 += bias2[col + 1]; }
            C[(size_t)row * ldc + col]           = acc[fm][fn][0] + b0;
            C[(size_t)row * ldc + col + 1]       = acc[fm][fn][1] + b1;
            C[(size_t)(row + 8) * ldc + col]     = acc[fm][fn][2] + b0;
            C[(size_t)(row + 8) * ldc + col + 1] = acc[fm][fn][3] + b1;
        }
}

// ---------------- fused energy GEMM + tanh + v-dot -> score[B,S] -------------
// Grid (8, 128): blockIdx.y = batch b, blockIdx.x = n-chunk (128 cols of H).
#define AS_STRIDE 40
#define AS_STAGE (128 * AS_STRIDE)
#define ATTN_SMEM_BYTES ((4 * 2 * AS_STAGE) * 2 + 128 * 4)

__global__ __launch_bounds__(256, 2) void attn_score_kernel(const float *__restrict__ v) {
    extern __shared__ __align__(16) __nv_bfloat16 smem[];
    __nv_bfloat16 *AsHi = smem;
    __nv_bfloat16 *AsLo = AsHi + 2 * AS_STAGE;
    __nv_bfloat16 *BsHi = AsLo + 2 * AS_STAGE;
    __nv_bfloat16 *BsLo = BsHi + 2 * AS_STAGE;
    float *red = (float *)(BsLo + 2 * AS_STAGE);

    const int b = blockIdx.y;
    const int n0 = blockIdx.x * 128;
    const int tid = threadIdx.x;
    const int lane = tid & 31;
    const int gid = lane >> 2;
    const int t4 = lane & 3;
    const int wm = (tid >> 5) >> 1;  // 0..3 (m tile of 32)
    const int wn = (tid >> 5) & 1;   // 0..1 (n tile of 64)
    if (tid < 128) red[tid] = 0.f;

    const int a_mrow = (lane & 15);
    const int a_koff = (lane >> 4) << 3;
    const int b_nrow = (lane & 7) + ((lane >> 4) << 3);
    const int b_koff = ((lane >> 3) & 1) << 3;

    const int ld_row = tid >> 2;
    const int ld_col = (tid & 3) << 3;

    float acc[2][8][4];
#pragma unroll
    for (int i = 0; i < 2; i++)
#pragma unroll
        for (int j = 0; j < 8; j++)
#pragma unroll
            for (int c = 0; c < 4; c++) acc[i][j][c] = 0.f;

#define LOAD_STAGE(st, k0)                                                     \
    do {                                                                       \
        _Pragma("unroll") for (int i = 0; i < 2; ++i) {                        \
            int row = ld_row + i * 64;                                         \
            size_t goA = (size_t)(b * 128 + row) * CH + (k0) + ld_col;         \
            size_t goB = (size_t)(n0 + row) * CH + (k0) + ld_col;              \
            uint32_t dof = (st) * AS_STAGE + row * AS_STRIDE + ld_col;         \
            CPASYNC16(s2u(AsHi + dof), g_enc_hi + goA);                        \
            CPASYNC16(s2u(AsLo + dof), g_enc_lo + goA);                        \
            CPASYNC16(s2u(BsHi + dof), g_w2_hi + goB);                         \
            CPASYNC16(s2u(BsLo + dof), g_w2_lo + goB);                         \
        }                                                                      \
        CPCOMMIT;                                                              \
    } while (0)

    LOAD_STAGE(0, 0);
    for (int kt = 0; kt < 32; ++kt) {
        if (kt + 1 < 32) {
            LOAD_STAGE((kt + 1) & 1, (kt + 1) * 32);
            CPWAIT1;
        } else {
            CPWAIT0;
        }
        __syncthreads();
        const int cur = kt & 1;
        const __nv_bfloat16 *cAH = AsHi + cur * AS_STAGE;
        const __nv_bfloat16 *cAL = AsLo + cur * AS_STAGE;
        const __nv_bfloat16 *cBH = BsHi + cur * AS_STAGE;
        const __nv_bfloat16 *cBL = BsLo + cur * AS_STAGE;
#pragma unroll
        for (int kk = 0; kk < 32; kk += 16) {
            uint32_t ah[2][4], al[2][4];
#pragma unroll
            for (int fm = 0; fm < 2; ++fm) {
                int rowb = wm * 32 + fm * 16 + a_mrow;
                ldsm4(ah[fm][0], ah[fm][1], ah[fm][2], ah[fm][3],
                      s2u(cAH + rowb * AS_STRIDE + kk + a_koff));
                ldsm4(al[fm][0], al[fm][1], al[fm][2], al[fm][3],
                      s2u(cAL + rowb * AS_STRIDE + kk + a_koff));
            }
#pragma unroll
            for (int fnp = 0; fnp < 4; ++fnp) {
                uint32_t bh[4], bl[4];
                int nrow = wn * 64 + fnp * 16 + b_nrow;
                ldsm4(bh[0], bh[1], bh[2], bh[3],
                      s2u(cBH + nrow * AS_STRIDE + kk + b_koff));
                ldsm4(bl[0], bl[1], bl[2], bl[3],
                      s2u(cBL + nrow * AS_STRIDE + kk + b_koff));
#pragma unroll
                for (int fm = 0; fm < 2; ++fm) {
                    float *d0 = acc[fm][fnp * 2];
                    float *d1 = acc[fm][fnp * 2 + 1];
                    MMA16816(d0, ah[fm][0], ah[fm][1], ah[fm][2], ah[fm][3], bh[0], bh[1]);
                    MMA16816(d0, ah[fm][0], ah[fm][1], ah[fm][2], ah[fm][3], bl[0], bl[1]);
                    MMA16816(d0, al[fm][0], al[fm][1], al[fm][2], al[fm][3], bh[0], bh[1]);
                    MMA16816(d1, ah[fm][0], ah[fm][1], ah[fm][2], ah[fm][3], bh[2], bh[3]);
                    MMA16816(d1, ah[fm][0], ah[fm][1], ah[fm][2], ah[fm][3], bl[2], bl[3]);
                    MMA16816(d1, al[fm][0], al[fm][1], al[fm][2], al[fm][3], bh[2], bh[3]);
                }
            }
        }
        __syncthreads();
    }

    const float *hWb = g_hW + (size_t)b * CH;
    float pA[2] = {0.f, 0.f}, pB[2] = {0.f, 0.f};
#pragma unroll
    for (int fm = 0; fm < 2; ++fm)
#pragma unroll
        for (int fn = 0; fn < 8; ++fn) {
            int col = n0 + wn * 64 + fn * 8 + (t4 << 1);
            float hw0 = hWb[col], hw1 = hWb[col + 1];
            float v0 = v[col], v1 = v[col + 1];
            pA[fm] += tanhf(acc[fm][fn][0] + hw0) * v0 +
                      tanhf(acc[fm][fn][1] + hw1) * v1;
            pB[fm] += tanhf(acc[fm][fn][2] + hw0) * v0 +
                      tanhf(acc[fm][fn][3] + hw1) * v1;
        }
#pragma unroll
    for (int fm = 0; fm < 2; ++fm)
#pragma unroll
        for (int j = 0; j < 2; ++j) {
            float val = j ? pB[fm] : pA[fm];
            val += __shfl_xor_sync(0xffffffffu, val, 1);
            val += __shfl_xor_sync(0xffffffffu, val, 2);
            if (t4 == 0) atomicAdd(&red[wm * 32 + fm * 16 + j * 8 + gid], val);
        }
    __syncthreads();
    if (tid < 128) atomicAdd(&g_score[b * 128 + tid], red[tid]);
}

// ---------------- softmax over S, writes attn output + weights in place ------
__global__ __launch_bounds__(128) void softmax_kernel(float *__restrict__ out_attn) {
    const int b = blockIdx.x;
    const int t = threadIdx.x;
    __shared__ float sm[128];
    float s = g_score[b * 128 + t];
    sm[t] = s;
    __syncthreads();
#pragma unroll
    for (int st = 64; st > 0; st >>= 1) {
        if (t < st) sm[t] = fmaxf(sm[t], sm[t + st]);
        __syncthreads();
    }
    float mx = sm[0];
    __syncthreads();
    float e = expf(s - mx);
    sm[t] = e;
    __syncthreads();
#pragma unroll
    for (int st = 64; st > 0; st >>= 1) {
        if (t < st) sm[t] += sm[t + st];
        __syncthreads();
    }
    float w = e / sm[0];
    g_score[b * 128 + t] = w;
    out_attn[b * 128 + t] = w;
}

// ---------------- context + assemble xin (bf16 split: emb|context|h_last) ----
__global__ __launch_bounds__(256) void context_kernel(
    const int *__restrict__ x, const float *__restrict__ emb_table,
    const float *__restrict__ hidden, const float *__restrict__ enc) {
    const int b = blockIdx.x;
    const int t = threadIdx.x;
    __shared__ float w_s[128];
    if (t < 128) w_s[t] = g_score[b * 128 + t];
    int tok = x[b];
    for (int i = t; i < CE; i += 256) {
        __nv_bfloat16 hi, lo;
        splitf(emb_table[(size_t)tok * CE + i], hi, lo);
        g_xin_hi[(size_t)b * 2560 + i] = hi;
        g_xin_lo[(size_t)b * 2560 + i] = lo;
    }
    for (int i = t; i < CH; i += 256) {
        __nv_bfloat16 hi, lo;
        splitf(hidden[(size_t)b * CH + i], hi, lo);
        g_xin_hi[(size_t)b * 2560 + 1536 + i] = hi;
        g_xin_lo[(size_t)b * 2560 + 1536 + i] = lo;
    }
    __syncthreads();
    float acc[4] = {0.f, 0.f, 0.f, 0.f};
    const float *encb = enc + (size_t)b * CS * CH;
    for (int s = 0; s < CS; ++s) {
        float w = w_s[s];
        const float *er = encb + (size_t)s * CH;
#pragma unroll
        for (int i = 0; i < 4; ++i) acc[i] += w * er[t + i * 256];
    }
#pragma unroll
    for (int i = 0; i < 4; ++i) {
        int h = t + i * 256;
        float c = acc[i];
        __nv_bfloat16 hi, lo;
        splitf(c, hi, lo);
        g_xin_hi[(size_t)b * 2560 + 512 + h] = hi;
        g_xin_lo[(size_t)b * 2560 + 512 + h] = lo;
        g_out2_hi[(size_t)b * 2048 + 1024 + h] = hi;
        g_out2_lo[(size_t)b * 2048 + 1024 + h] = lo;
    }
}

// ---------------- LSTM pointwise ---------------------------------------------
__global__ __launch_bounds__(256) void lstm_kernel(
    const float *__restrict__ cell, float *__restrict__ out_h,
    float *__restrict__ out_c) {
    int id = blockIdx.x * 256 + threadIdx.x;  // 131072
    int b = id >> 10;
    int h = id & 1023;
    const float *gt = g_gates + (size_t)b * 4096;
    float gi = gt[h], gf = gt[1024 + h], gg = gt[2048 + h], go = gt[3072 + h];
    float c_old = cell[(size_t)b * CH + h];
    float cn = sigf(gf) * c_old + sigf(gi) * tanhf(gg);
    float hn = sigf(go) * tanhf(cn);
    out_h[(size_t)b * CH + h] = hn;
    out_c[(size_t)b * CH + h] = cn;
    __nv_bfloat16 hi, lo;
    splitf(hn, hi, lo);
    g_out2_hi[(size_t)b * 2048 + h] = hi;
    g_out2_lo[(size_t)b * 2048 + h] = lo;
}

// ---------------- launch ------------------------------------------------------
extern "C" void kernel_launch(void *const *d_in, const int *in_sizes, int n_in,
                              void *d_out, int out_size) {
    (void)in_sizes; (void)n_in; (void)out_size;
    const int *x           = (const int *)d_in[0];
    const float *hidden    = (const float *)d_in[1];
    const float *cell      = (const float *)d_in[2];
    const float *enc       = (const float *)d_in[3];
    const float *emb_table = (const float *)d_in[4];
    const float *attn_W    = (const float *)d_in[5];
    const float *attn_b    = (const float *)d_in[6];
    const float *v         = (const float *)d_in[7];
    const float *W_ih      = (const float *)d_in[8];
    const float *W_hh      = (const float *)d_in[9];
    const float *b_ih      = (const float *)d_in[10];
    const float *b_hh      = (const float *)d_in[11];
    const float *fc_W      = (const float *)d_in[12];
    const float *fc_b      = (const float *)d_in[13];

    float *out        = (float *)d_out;
    float *out_logits = out;
    float *out_h      = out + (size_t)CB * CV;
    float *out_c      = out_h + (size_t)CB * CH;
    float *out_attn   = out_c + (size_t)CB * CH;

    float *gatesp = nullptr;
    __nv_bfloat16 *o2h = nullptr, *o2l = nullptr, *xih = nullptr, *xil = nullptr;
    cudaGetSymbolAddress((void **)&gatesp, g_gates);
    cudaGetSymbolAddress((void **)&o2h, g_out2_hi);
    cudaGetSymbolAddress((void **)&o2l, g_out2_lo);
    cudaGetSymbolAddress((void **)&xih, g_xin_hi);
    cudaGetSymbolAddress((void **)&xil, g_xin_lo);

    cudaFuncSetAttribute(attn_score_kernel,
                         cudaFuncAttributeMaxDynamicSharedMemorySize,
                         ATTN_SMEM_BYTES);
    cudaFuncSetAttribute(gemm2_kernel,
                         cudaFuncAttributeMaxDynamicSharedMemorySize,
                         G2_SMEM_BYTES);

    // 1) precision-split encoder_outputs
    conv_enc_kernel<<<16384, 256>>>(enc);
    // 2) split attn_W[:, H:2H] + zero score + seed g_hW with bias
    conv_w2_kernel<<<1024, 256>>>(attn_W, attn_b);
    // 3) hW += h_last @ attn_W[:, :H]^T  (K-split x4, atomic)
    hw_kernel<<<dim3(64, 4), 256>>>(hidden, attn_W);
    // 4) fused energy GEMM + tanh + v-dot -> g_score  (launch #4: profiled)
    attn_score_kernel<<<dim3(8, CB), 256, ATTN_SMEM_BYTES>>>(v);
    // 5) softmax -> attn_weights output
    softmax_kernel<<<CB, 128>>>(out_attn);
    // 6) context + xin assembly (bf16 split)
    context_kernel<<<CB, 256>>>(x, emb_table, hidden, enc);
    // 7) gates = xin @ [W_ih|W_hh]^T + b_ih + b_hh  (K = 1536 + 1024)
    gemm2_kernel<<<4096 / 64, 256, G2_SMEM_BYTES>>>(
        xih, xil, 2560,
        W_ih, 1536, 1536, W_hh, CH,
        b_ih, b_hh, gatesp, 4096, 2560);
    // 8) LSTM pointwise
    lstm_kernel<<<(CB * CH) / 256, 256>>>(cell, out_h, out_c);
    // 9) logits = [h_new|context] @ fc_W^T + fc_b
    gemm2_kernel<<<CV / 64, 256, G2_SMEM_BYTES>>>(
        o2h, o2l, 2048,
        fc_W, 2048, 2048, nullptr, 0,
        fc_b, nullptr, out_logits, CV, 2048);
}